// round 7
// baseline (speedup 1.0000x reference)
#include <cuda_runtime.h>
#include <cuda_bf16.h>
#include <stdint.h>
#include <math.h>

// ---------------------------------------------------------------------------
// MySelfAttention_V2 (B=4, N=4096, D=768) — mma.sync bf16 hi/lo split (3-pass)
// GEMM: C = alpha * A*B^T (+bias), A,B as bf16 (hi,lo) pairs, fp32 accum:
//   A*B ≈ Ah*Bh + Ah*Bl + Al*Bh     (dropped term ~2^-18 rel)
// R7: register-level software pipeline — interleave A-fragment ldmatrix with
//     MMA bursts (12 MMAs between 2 ldsm) to hide shared-memory latency.
// ---------------------------------------------------------------------------

#define B_   4
#define N_   4096
#define D_   768
#define QKVC 2304
#define SCALE_F 0.03608439182435161f

typedef __nv_bfloat16 bf16;

// ---------------- scratch (static device globals: allocation-guard-safe) ----
__device__ float g_qkv [(size_t)B_ * N_ * QKVC];
__device__ float g_s   [(size_t)B_ * N_ * N_];
__device__ bf16  g_xh  [(size_t)B_ * N_ * D_],   g_xl  [(size_t)B_ * N_ * D_];
__device__ bf16  g_qh  [(size_t)B_ * N_ * QKVC], g_ql  [(size_t)B_ * N_ * QKVC];
__device__ bf16  g_sh  [(size_t)B_ * N_ * N_],   g_sl  [(size_t)B_ * N_ * N_];
__device__ bf16  g_vth [(size_t)B_ * D_ * N_],   g_vtl [(size_t)B_ * D_ * N_];
__device__ bf16  g_ch  [(size_t)B_ * N_ * D_],   g_cl  [(size_t)B_ * N_ * D_];
__device__ bf16  g_wqh [(size_t)QKVC * D_],      g_wql [(size_t)QKVC * D_];
__device__ bf16  g_woh [(size_t)D_ * D_],        g_wol [(size_t)D_ * D_];

// ---------------- PTX helpers ----------------------------------------------
static __device__ __forceinline__ uint32_t smem_u32(const void* p) {
    uint32_t a;
    asm("{ .reg .u64 t; cvta.to.shared.u64 t, %1; cvt.u32.u64 %0, t; }"
        : "=r"(a) : "l"(p));
    return a;
}
static __device__ __forceinline__ void cp_async16(uint32_t saddr, const void* g) {
    asm volatile("cp.async.cg.shared.global [%0], [%1], 16;"
                 :: "r"(saddr), "l"(g) : "memory");
}
static __device__ __forceinline__ void cp_commit() {
    asm volatile("cp.async.commit_group;" ::: "memory");
}
template <int N>
static __device__ __forceinline__ void cp_wait() {
    asm volatile("cp.async.wait_group %0;" :: "n"(N) : "memory");
}
static __device__ __forceinline__ void ldsm_x4(uint32_t* r, uint32_t addr) {
    asm volatile("ldmatrix.sync.aligned.m8n8.x4.shared.b16 {%0,%1,%2,%3}, [%4];"
                 : "=r"(r[0]), "=r"(r[1]), "=r"(r[2]), "=r"(r[3]) : "r"(addr));
}
static __device__ __forceinline__ void mma16816(float* c, const uint32_t* a,
                                                const uint32_t* b) {
    asm volatile(
        "mma.sync.aligned.m16n8k16.row.col.f32.bf16.bf16.f32 "
        "{%0,%1,%2,%3}, {%4,%5,%6,%7}, {%8,%9}, {%0,%1,%2,%3};"
        : "+f"(c[0]), "+f"(c[1]), "+f"(c[2]), "+f"(c[3])
        : "r"(a[0]), "r"(a[1]), "r"(a[2]), "r"(a[3]), "r"(b[0]), "r"(b[1]));
}
// hi/lo split of an fp32 into two bf16
static __device__ __forceinline__ void split1(float v, bf16& h, bf16& l) {
    h = __float2bfloat16_rn(v);
    l = __float2bfloat16_rn(v - __bfloat162float(h));
}
static __device__ __forceinline__ uint32_t pack2(bf16 a, bf16 b) {
    return (uint32_t)__bfloat16_as_ushort(a) |
           ((uint32_t)__bfloat16_as_ushort(b) << 16);
}

// XOR swizzle: logical (row, 16B-chunk) -> byte offset in 64B-row tile.
static __device__ __forceinline__ uint32_t swz(uint32_t row, uint32_t chunk) {
    return row * 64u + (((chunk ^ (row >> 1)) & 3u) << 4);
}

// ---------------------------------------------------------------------------
// GEMM: C[m,n] = alpha * sum_k A[m,k]*B[n,k]  (+bias[n])
// A,B bf16 hi/lo K-major. Tile 128x128, BK=32, 256 threads (2x4 warps),
// 3-stage cp.async pipeline, swizzled 64B smem rows, A-fragment reg pipeline.
// ---------------------------------------------------------------------------
#define TILE_B 8192                       // 128 rows * 64 B
#define STAGE_B (4 * TILE_B)              // Ah,Al,Bh,Bl
static const int SMEM_DYN = 3 * STAGE_B;  // 98304

template <bool HAS_BIAS, bool WRITE_F32, bool WRITE_SPLIT>
__global__ __launch_bounds__(256)
void mma_gemm(const bf16* __restrict__ Ah, const bf16* __restrict__ Al,
              const bf16* __restrict__ Bh, const bf16* __restrict__ Bl,
              const float* __restrict__ bias, float* __restrict__ C,
              bf16* __restrict__ Oh, bf16* __restrict__ Ol,
              int K, int lda, int ldb, int ldc,
              long long sA, long long sB, long long sC, float alpha)
{
    extern __shared__ char smem[];
    const uint32_t sb = smem_u32(smem);

    Ah += blockIdx.z * sA;  Al += blockIdx.z * sA;
    Bh += blockIdx.z * sB;  Bl += blockIdx.z * sB;
    const long long cz = blockIdx.z * sC;
    const int m0 = blockIdx.y * 128, n0 = blockIdx.x * 128;
    const int tid  = threadIdx.x;
    const int wid  = tid >> 5, lane = tid & 31;
    const int wm   = wid >> 2, wn = wid & 3;   // 2 x 4 warps

    // cp.async mapping: per matrix, 2x 16B per thread (rows r, r+64; chunk t&3)
    const int cr0 = tid >> 2, cc = tid & 3;
    const uint32_t so0 = swz((uint32_t)cr0, (uint32_t)cc);
    const uint32_t so1 = swz((uint32_t)(cr0 + 64), (uint32_t)cc);

#define LOAD_STAGE(st, k0)                                                      \
    do {                                                                        \
        const uint32_t s0 = sb + (uint32_t)(st) * STAGE_B;                      \
        const long long kof = (long long)(k0) + cc * 8;                         \
        cp_async16(s0 + 0*TILE_B + so0, Ah + (long long)(m0+cr0)    *lda + kof);\
        cp_async16(s0 + 0*TILE_B + so1, Ah + (long long)(m0+cr0+64) *lda + kof);\
        cp_async16(s0 + 1*TILE_B + so0, Al + (long long)(m0+cr0)    *lda + kof);\
        cp_async16(s0 + 1*TILE_B + so1, Al + (long long)(m0+cr0+64) *lda + kof);\
        cp_async16(s0 + 2*TILE_B + so0, Bh + (long long)(n0+cr0)    *ldb + kof);\
        cp_async16(s0 + 2*TILE_B + so1, Bh + (long long)(n0+cr0+64) *ldb + kof);\
        cp_async16(s0 + 3*TILE_B + so0, Bl + (long long)(n0+cr0)    *ldb + kof);\
        cp_async16(s0 + 3*TILE_B + so1, Bl + (long long)(n0+cr0+64) *ldb + kof);\
    } while (0)

    // ldmatrix lane-logical coordinates (same mapping as validated R5/R6)
    const uint32_t a_row_l = (uint32_t)(lane & 15);
    const uint32_t a_chk_l = (uint32_t)(lane >> 4);
    const uint32_t b_row_l = (uint32_t)((lane & 7) + ((lane >> 4) << 3));
    const uint32_t b_chk_l = (uint32_t)((lane >> 3) & 1);

    float acc[4][4][4];
#pragma unroll
    for (int mt = 0; mt < 4; mt++)
#pragma unroll
        for (int nt = 0; nt < 4; nt++)
#pragma unroll
            for (int r = 0; r < 4; r++) acc[mt][nt][r] = 0.0f;

    const int nch = K / 32;
    LOAD_STAGE(0, 0);
    cp_commit();
    if (nch > 1) LOAD_STAGE(1, 32);
    cp_commit();

    int st = 0;                        // compute stage
    int ls = 2;                        // load stage
    for (int ch = 0; ch < nch; ch++) {
        cp_wait<1>();                  // stage `st` resident
        __syncthreads();               // all warps done with stage `ls` contents
        if (ch + 2 < nch) LOAD_STAGE(ls, (long long)(ch + 2) * 32);
        cp_commit();

        const uint32_t base = sb + (uint32_t)st * STAGE_B;
#pragma unroll
        for (int kk = 0; kk < 2; kk++) {
            const uint32_t a_chk = (uint32_t)(kk * 2) + a_chk_l;
            const uint32_t b_chk = (uint32_t)(kk * 2) + b_chk_l;

            // B fragments (held for whole kk): hi + lo, 2 n-pairs each
            uint32_t bh_[2][4], bl_[2][4];
#pragma unroll
            for (int p = 0; p < 2; p++) {
                const uint32_t ro = swz((uint32_t)(wn * 32 + p * 16) + b_row_l, b_chk);
                ldsm_x4(bh_[p], base + 2 * TILE_B + ro);
                ldsm_x4(bl_[p], base + 3 * TILE_B + ro);
            }

            // A-fragment register pipeline: load mt+1 while computing mt
            uint32_t acur[2][4], anxt[2][4];
            {
                const uint32_t ro = swz((uint32_t)(wm * 64) + a_row_l, a_chk);
                ldsm_x4(acur[0], base + 0 * TILE_B + ro);  // hi
                ldsm_x4(acur[1], base + 1 * TILE_B + ro);  // lo
            }
#pragma unroll
            for (int mt = 0; mt < 4; mt++) {
                if (mt < 3) {
                    const uint32_t ro =
                        swz((uint32_t)(wm * 64 + (mt + 1) * 16) + a_row_l, a_chk);
                    ldsm_x4(anxt[0], base + 0 * TILE_B + ro);
                    ldsm_x4(anxt[1], base + 1 * TILE_B + ro);
                }
                // 3 passes: (Ah,Bh), (Ah,Bl), (Al,Bh)
#pragma unroll
                for (int ps = 0; ps < 3; ps++) {
                    const uint32_t* a = acur[ps == 2 ? 1 : 0];
                    uint32_t (*bb)[4] = (ps == 1) ? bl_ : bh_;
#pragma unroll
                    for (int nt = 0; nt < 4; nt++)
                        mma16816(acc[mt][nt], a, &bb[nt >> 1][(nt & 1) * 2]);
                }
                if (mt < 3) {
#pragma unroll
                    for (int r = 0; r < 4; r++) {
                        acur[0][r] = anxt[0][r];
                        acur[1][r] = anxt[1][r];
                    }
                }
            }
        }
        st = (st == 2) ? 0 : st + 1;
        ls = (ls == 2) ? 0 : ls + 1;
    }

    // ---- epilogue ----
    const int tq = lane >> 2, tr = lane & 3;
#pragma unroll
    for (int nt = 0; nt < 4; nt++) {
        const int n = n0 + wn * 32 + nt * 8 + tr * 2;
        float b0 = 0.f, b1 = 0.f;
        if (HAS_BIAS) { b0 = bias[n]; b1 = bias[n + 1]; }
#pragma unroll
        for (int mt = 0; mt < 4; mt++) {
            const int m = m0 + wm * 64 + mt * 16 + tq;
            float2 o0, o1;
            o0.x = fmaf(alpha, acc[mt][nt][0], b0);
            o0.y = fmaf(alpha, acc[mt][nt][1], b1);
            o1.x = fmaf(alpha, acc[mt][nt][2], b0);
            o1.y = fmaf(alpha, acc[mt][nt][3], b1);
            const long long r0 = cz + (long long)m * ldc + n;
            const long long r1 = cz + (long long)(m + 8) * ldc + n;
            if (WRITE_F32) {
                *(float2*)(C + r0) = o0;
                *(float2*)(C + r1) = o1;
            }
            if (WRITE_SPLIT) {
                bf16 h0, l0, h1, l1;
                split1(o0.x, h0, l0); split1(o0.y, h1, l1);
                *(uint32_t*)(Oh + r0) = pack2(h0, h1);
                *(uint32_t*)(Ol + r0) = pack2(l0, l1);
                split1(o1.x, h0, l0); split1(o1.y, h1, l1);
                *(uint32_t*)(Oh + r1) = pack2(h0, h1);
                *(uint32_t*)(Ol + r1) = pack2(l0, l1);
            }
        }
    }
#undef LOAD_STAGE
}

// ---------------------------------------------------------------------------
// elementwise fp32 -> bf16 hi/lo split
// ---------------------------------------------------------------------------
__global__ __launch_bounds__(256)
void split_kernel(const float* __restrict__ in, bf16* __restrict__ oh,
                  bf16* __restrict__ ol)
{
    const size_t i = ((size_t)blockIdx.x * 256 + threadIdx.x) * 4;
    const float4 v = *(const float4*)(in + i);
    bf16 h0, h1, h2, h3, l0, l1, l2, l3;
    split1(v.x, h0, l0); split1(v.y, h1, l1);
    split1(v.z, h2, l2); split1(v.w, h3, l3);
    *(uint2*)(oh + i) = make_uint2(pack2(h0, h1), pack2(h2, h3));
    *(uint2*)(ol + i) = make_uint2(pack2(l0, l1), pack2(l2, l3));
}

// ---------------------------------------------------------------------------
// transpose + split:  in [R][C] (row stride ldin) -> oh/ol [C][R]
// ---------------------------------------------------------------------------
__global__ __launch_bounds__(256)
void transpose_split(const float* __restrict__ in, int ldin, long long sIn,
                     bf16* __restrict__ oh, bf16* __restrict__ ol,
                     int R, long long sOut)
{
    __shared__ float t[32][33];
    in += blockIdx.z * sIn;
    oh += blockIdx.z * sOut;
    ol += blockIdx.z * sOut;
    const int c0 = blockIdx.x * 32, r0 = blockIdx.y * 32;
    const int x = threadIdx.x, y = threadIdx.y;
#pragma unroll
    for (int j = 0; j < 32; j += 8)
        t[y + j][x] = in[(long long)(r0 + y + j) * ldin + c0 + x];
    __syncthreads();
#pragma unroll
    for (int j = 0; j < 32; j += 8) {
        const float v = t[x][y + j];
        bf16 h, l;
        split1(v, h, l);
        oh[(long long)(c0 + y + j) * R + r0 + x] = h;
        ol[(long long)(c0 + y + j) * R + r0 + x] = l;
    }
}

// ---------------------------------------------------------------------------
// row softmax over S (fp32) -> bf16 hi/lo outputs
// ---------------------------------------------------------------------------
__global__ __launch_bounds__(256)
void softmax_split_kernel(const float* __restrict__ S, bf16* __restrict__ Sh,
                          bf16* __restrict__ Sl)
{
    const size_t ro = (size_t)blockIdx.x * N_;
    const float* p = S + ro;
    const int tid = threadIdx.x;
    const int w = tid >> 5, l = tid & 31;

    float4 v[4];
#pragma unroll
    for (int i = 0; i < 4; i++)
        v[i] = *(const float4*)(p + (size_t)(tid + i * 256) * 4);

    float m = v[0].x;
#pragma unroll
    for (int i = 0; i < 4; i++) {
        m = fmaxf(m, v[i].x); m = fmaxf(m, v[i].y);
        m = fmaxf(m, v[i].z); m = fmaxf(m, v[i].w);
    }
#pragma unroll
    for (int o = 16; o > 0; o >>= 1)
        m = fmaxf(m, __shfl_xor_sync(0xffffffffu, m, o));

    __shared__ float red[8];
    if (l == 0) red[w] = m;
    __syncthreads();
    float bm = red[0];
#pragma unroll
    for (int i = 1; i < 8; i++) bm = fmaxf(bm, red[i]);
    __syncthreads();

    float s = 0.0f;
#pragma unroll
    for (int i = 0; i < 4; i++) {
        v[i].x = expf(v[i].x - bm); s += v[i].x;
        v[i].y = expf(v[i].y - bm); s += v[i].y;
        v[i].z = expf(v[i].z - bm); s += v[i].z;
        v[i].w = expf(v[i].w - bm); s += v[i].w;
    }
#pragma unroll
    for (int o = 16; o > 0; o >>= 1)
        s += __shfl_xor_sync(0xffffffffu, s, o);
    if (l == 0) red[w] = s;
    __syncthreads();
    float tot = red[0];
#pragma unroll
    for (int i = 1; i < 8; i++) tot += red[i];
    const float inv = 1.0f / tot;

#pragma unroll
    for (int i = 0; i < 4; i++) {
        const size_t o = ro + (size_t)(tid + i * 256) * 4;
        bf16 h0, h1, h2, h3, l0, l1, l2, l3;
        split1(v[i].x * inv, h0, l0);
        split1(v[i].y * inv, h1, l1);
        split1(v[i].z * inv, h2, l2);
        split1(v[i].w * inv, h3, l3);
        *(uint2*)(Sh + o) = make_uint2(pack2(h0, h1), pack2(h2, h3));
        *(uint2*)(Sl + o) = make_uint2(pack2(l0, l1), pack2(l2, l3));
    }
}

// ---------------------------------------------------------------------------
extern "C" void kernel_launch(void* const* d_in, const int* in_sizes, int n_in,
                              void* d_out, int out_size)
{
    const float* x     = (const float*)d_in[0];
    const float* w_qkv = (const float*)d_in[1];
    const float* b_qkv = (const float*)d_in[2];
    const float* w_out = (const float*)d_in[3];
    const float* b_out = (const float*)d_in[4];
    float* out = (float*)d_out;

    float *qkv, *S;
    bf16 *xh, *xl, *qh, *ql, *sh, *sl, *vth, *vtl, *ch, *cl, *wqh, *wql, *woh, *wol;
    cudaGetSymbolAddress((void**)&qkv, g_qkv);
    cudaGetSymbolAddress((void**)&S,   g_s);
    cudaGetSymbolAddress((void**)&xh,  g_xh);  cudaGetSymbolAddress((void**)&xl,  g_xl);
    cudaGetSymbolAddress((void**)&qh,  g_qh);  cudaGetSymbolAddress((void**)&ql,  g_ql);
    cudaGetSymbolAddress((void**)&sh,  g_sh);  cudaGetSymbolAddress((void**)&sl,  g_sl);
    cudaGetSymbolAddress((void**)&vth, g_vth); cudaGetSymbolAddress((void**)&vtl, g_vtl);
    cudaGetSymbolAddress((void**)&ch,  g_ch);  cudaGetSymbolAddress((void**)&cl,  g_cl);
    cudaGetSymbolAddress((void**)&wqh, g_wqh); cudaGetSymbolAddress((void**)&wql, g_wql);
    cudaGetSymbolAddress((void**)&woh, g_woh); cudaGetSymbolAddress((void**)&wol, g_wol);

    cudaFuncSetAttribute(mma_gemm<true, true, true>,
        cudaFuncAttributeMaxDynamicSharedMemorySize, SMEM_DYN);
    cudaFuncSetAttribute(mma_gemm<false, true, false>,
        cudaFuncAttributeMaxDynamicSharedMemorySize, SMEM_DYN);
    cudaFuncSetAttribute(mma_gemm<false, false, true>,
        cudaFuncAttributeMaxDynamicSharedMemorySize, SMEM_DYN);
    cudaFuncSetAttribute(mma_gemm<true, true, false>,
        cudaFuncAttributeMaxDynamicSharedMemorySize, SMEM_DYN);

    const dim3 blk(256);
    const dim3 tblk(32, 8);

    // operand prep
    split_kernel<<<(B_ * N_ * D_) / 1024, blk>>>(x, xh, xl);
    transpose_split<<<dim3(QKVC / 32, D_ / 32, 1), tblk>>>(
        w_qkv, QKVC, 0, wqh, wql, D_, 0);
    transpose_split<<<dim3(D_ / 32, D_ / 32, 1), tblk>>>(
        w_out, D_, 0, woh, wol, D_, 0);

    // 1) qkv = x @ w_qkv + b_qkv   (fp32 + fused hi/lo split)
    mma_gemm<true, true, true><<<dim3(QKVC / 128, (B_ * N_) / 128, 1), blk, SMEM_DYN>>>(
        xh, xl, wqh, wql, b_qkv, qkv, qh, ql, D_, D_, D_, QKVC, 0, 0, 0, 1.0f);

    // V^T (per batch): qkv[b][n][2D..3D) -> [D][N]
    transpose_split<<<dim3(D_ / 32, N_ / 32, B_), tblk>>>(
        qkv + 2 * D_, QKVC, (long long)N_ * QKVC, vth, vtl, N_,
        (long long)D_ * N_);

    // 2) S = scale * Q @ K^T
    mma_gemm<false, true, false><<<dim3(N_ / 128, N_ / 128, B_), blk, SMEM_DYN>>>(
        qh, ql, qh + D_, ql + D_, nullptr, S, nullptr, nullptr, D_, QKVC, QKVC, N_,
        (long long)N_ * QKVC, (long long)N_ * QKVC, (long long)N_ * N_, SCALE_F);

    // 3) softmax + split
    softmax_split_kernel<<<B_ * N_, blk>>>(S, sh, sl);

    // 4) ctx = S @ V   (hi/lo split only, no fp32 intermediate)
    mma_gemm<false, false, true><<<dim3(D_ / 128, N_ / 128, B_), blk, SMEM_DYN>>>(
        sh, sl, vth, vtl, nullptr, nullptr, ch, cl, N_, N_, N_, D_,
        (long long)N_ * N_, (long long)D_ * N_, (long long)N_ * D_, 1.0f);

    // 5) out = ctx @ w_out + b_out
    mma_gemm<true, true, false><<<dim3(D_ / 128, (B_ * N_) / 128, 1), blk, SMEM_DYN>>>(
        ch, cl, woh, wol, b_out, out, nullptr, nullptr, D_, D_, D_, D_, 0, 0, 0, 1.0f);
}

// round 8
// speedup vs baseline: 1.0467x; 1.0467x over previous
#include <cuda_runtime.h>
#include <cuda_bf16.h>
#include <stdint.h>
#include <math.h>

// ---------------------------------------------------------------------------
// MySelfAttention_V2 (B=4, N=4096, D=768) — mma.sync bf16 hi/lo split (3-pass)
// GEMM: C = alpha * A*B^T (+bias), A,B as bf16 (hi,lo) pairs, fp32 accum:
//   A*B ≈ Ah*Bh + Ah*Bl + Al*Bh     (dropped term ~2^-18 rel)
// R8: revert R7 reg-pipeline (cost 2-CTA occupancy); pin __launch_bounds__(256,2);
//     drop fp32 qkv intermediate — V^T transposed directly from bf16 planes.
// ---------------------------------------------------------------------------

#define B_   4
#define N_   4096
#define D_   768
#define QKVC 2304
#define SCALE_F 0.03608439182435161f

typedef __nv_bfloat16 bf16;

// ---------------- scratch (static device globals: allocation-guard-safe) ----
__device__ float g_s   [(size_t)B_ * N_ * N_];
__device__ bf16  g_xh  [(size_t)B_ * N_ * D_],   g_xl  [(size_t)B_ * N_ * D_];
__device__ bf16  g_qh  [(size_t)B_ * N_ * QKVC], g_ql  [(size_t)B_ * N_ * QKVC];
__device__ bf16  g_sh  [(size_t)B_ * N_ * N_],   g_sl  [(size_t)B_ * N_ * N_];
__device__ bf16  g_vth [(size_t)B_ * D_ * N_],   g_vtl [(size_t)B_ * D_ * N_];
__device__ bf16  g_ch  [(size_t)B_ * N_ * D_],   g_cl  [(size_t)B_ * N_ * D_];
__device__ bf16  g_wqh [(size_t)QKVC * D_],      g_wql [(size_t)QKVC * D_];
__device__ bf16  g_woh [(size_t)D_ * D_],        g_wol [(size_t)D_ * D_];

// ---------------- PTX helpers ----------------------------------------------
static __device__ __forceinline__ uint32_t smem_u32(const void* p) {
    uint32_t a;
    asm("{ .reg .u64 t; cvta.to.shared.u64 t, %1; cvt.u32.u64 %0, t; }"
        : "=r"(a) : "l"(p));
    return a;
}
static __device__ __forceinline__ void cp_async16(uint32_t saddr, const void* g) {
    asm volatile("cp.async.cg.shared.global [%0], [%1], 16;"
                 :: "r"(saddr), "l"(g) : "memory");
}
static __device__ __forceinline__ void cp_commit() {
    asm volatile("cp.async.commit_group;" ::: "memory");
}
template <int N>
static __device__ __forceinline__ void cp_wait() {
    asm volatile("cp.async.wait_group %0;" :: "n"(N) : "memory");
}
static __device__ __forceinline__ void ldsm_x4(uint32_t* r, uint32_t addr) {
    asm volatile("ldmatrix.sync.aligned.m8n8.x4.shared.b16 {%0,%1,%2,%3}, [%4];"
                 : "=r"(r[0]), "=r"(r[1]), "=r"(r[2]), "=r"(r[3]) : "r"(addr));
}
static __device__ __forceinline__ void mma16816(float* c, const uint32_t* a,
                                                const uint32_t* b) {
    asm volatile(
        "mma.sync.aligned.m16n8k16.row.col.f32.bf16.bf16.f32 "
        "{%0,%1,%2,%3}, {%4,%5,%6,%7}, {%8,%9}, {%0,%1,%2,%3};"
        : "+f"(c[0]), "+f"(c[1]), "+f"(c[2]), "+f"(c[3])
        : "r"(a[0]), "r"(a[1]), "r"(a[2]), "r"(a[3]), "r"(b[0]), "r"(b[1]));
}
// hi/lo split of an fp32 into two bf16
static __device__ __forceinline__ void split1(float v, bf16& h, bf16& l) {
    h = __float2bfloat16_rn(v);
    l = __float2bfloat16_rn(v - __bfloat162float(h));
}
static __device__ __forceinline__ uint32_t pack2(bf16 a, bf16 b) {
    return (uint32_t)__bfloat16_as_ushort(a) |
           ((uint32_t)__bfloat16_as_ushort(b) << 16);
}

// XOR swizzle: logical (row, 16B-chunk) -> byte offset in 64B-row tile.
static __device__ __forceinline__ uint32_t swz(uint32_t row, uint32_t chunk) {
    return row * 64u + (((chunk ^ (row >> 1)) & 3u) << 4);
}

// ---------------------------------------------------------------------------
// GEMM: C[m,n] = alpha * sum_k A[m,k]*B[n,k]  (+bias[n])
// A,B bf16 hi/lo K-major. Tile 128x128, BK=32, 256 threads (2x4 warps),
// 3-stage cp.async pipeline, swizzled 64B smem rows. (R6 inner loop.)
// ---------------------------------------------------------------------------
#define TILE_B 8192                       // 128 rows * 64 B
#define STAGE_B (4 * TILE_B)              // Ah,Al,Bh,Bl
static const int SMEM_DYN = 3 * STAGE_B;  // 98304

template <bool HAS_BIAS, bool WRITE_F32, bool WRITE_SPLIT>
__global__ __launch_bounds__(256, 2)
void mma_gemm(const bf16* __restrict__ Ah, const bf16* __restrict__ Al,
              const bf16* __restrict__ Bh, const bf16* __restrict__ Bl,
              const float* __restrict__ bias, float* __restrict__ C,
              bf16* __restrict__ Oh, bf16* __restrict__ Ol,
              int K, int lda, int ldb, int ldc,
              long long sA, long long sB, long long sC, float alpha)
{
    extern __shared__ char smem[];
    const uint32_t sb = smem_u32(smem);

    Ah += blockIdx.z * sA;  Al += blockIdx.z * sA;
    Bh += blockIdx.z * sB;  Bl += blockIdx.z * sB;
    const long long cz = blockIdx.z * sC;
    const int m0 = blockIdx.y * 128, n0 = blockIdx.x * 128;
    const int tid  = threadIdx.x;
    const int wid  = tid >> 5, lane = tid & 31;
    const int wm   = wid >> 2, wn = wid & 3;   // 2 x 4 warps

    // cp.async mapping: per matrix, 2x 16B per thread (rows r, r+64; chunk t&3)
    const int cr0 = tid >> 2, cc = tid & 3;
    const uint32_t so0 = swz((uint32_t)cr0, (uint32_t)cc);
    const uint32_t so1 = swz((uint32_t)(cr0 + 64), (uint32_t)cc);

#define LOAD_STAGE(st, k0)                                                      \
    do {                                                                        \
        const uint32_t s0 = sb + (uint32_t)(st) * STAGE_B;                      \
        const long long kof = (long long)(k0) + cc * 8;                         \
        cp_async16(s0 + 0*TILE_B + so0, Ah + (long long)(m0+cr0)    *lda + kof);\
        cp_async16(s0 + 0*TILE_B + so1, Ah + (long long)(m0+cr0+64) *lda + kof);\
        cp_async16(s0 + 1*TILE_B + so0, Al + (long long)(m0+cr0)    *lda + kof);\
        cp_async16(s0 + 1*TILE_B + so1, Al + (long long)(m0+cr0+64) *lda + kof);\
        cp_async16(s0 + 2*TILE_B + so0, Bh + (long long)(n0+cr0)    *ldb + kof);\
        cp_async16(s0 + 2*TILE_B + so1, Bh + (long long)(n0+cr0+64) *ldb + kof);\
        cp_async16(s0 + 3*TILE_B + so0, Bl + (long long)(n0+cr0)    *ldb + kof);\
        cp_async16(s0 + 3*TILE_B + so1, Bl + (long long)(n0+cr0+64) *ldb + kof);\
    } while (0)

    // ldmatrix lane-logical coordinates (validated R5/R6 mapping)
    const uint32_t a_row_l = (uint32_t)(lane & 15);
    const uint32_t a_chk_l = (uint32_t)(lane >> 4);
    const uint32_t b_row_l = (uint32_t)((lane & 7) + ((lane >> 4) << 3));
    const uint32_t b_chk_l = (uint32_t)((lane >> 3) & 1);

    float acc[4][4][4];
#pragma unroll
    for (int mt = 0; mt < 4; mt++)
#pragma unroll
        for (int nt = 0; nt < 4; nt++)
#pragma unroll
            for (int r = 0; r < 4; r++) acc[mt][nt][r] = 0.0f;

    const int nch = K / 32;
    LOAD_STAGE(0, 0);
    cp_commit();
    if (nch > 1) LOAD_STAGE(1, 32);
    cp_commit();

    int st = 0;                        // compute stage
    int ls = 2;                        // load stage
    for (int ch = 0; ch < nch; ch++) {
        cp_wait<1>();                  // stage `st` resident
        __syncthreads();               // all warps done with stage `ls` contents
        if (ch + 2 < nch) LOAD_STAGE(ls, (long long)(ch + 2) * 32);
        cp_commit();

        const uint32_t base = sb + (uint32_t)st * STAGE_B;
#pragma unroll
        for (int kk = 0; kk < 2; kk++) {
            uint32_t af[2][4][4];      // [hl][mt][reg]
            uint32_t bfr[2][2][4];     // [hl][pair][reg]
            const uint32_t a_chk = (uint32_t)(kk * 2) + a_chk_l;
            const uint32_t b_chk = (uint32_t)(kk * 2) + b_chk_l;
#pragma unroll
            for (int mt = 0; mt < 4; mt++) {
                const uint32_t ro = swz((uint32_t)(wm * 64 + mt * 16) + a_row_l, a_chk);
                ldsm_x4(af[0][mt], base + 0 * TILE_B + ro);
                ldsm_x4(af[1][mt], base + 1 * TILE_B + ro);
            }
#pragma unroll
            for (int p = 0; p < 2; p++) {
                const uint32_t ro = swz((uint32_t)(wn * 32 + p * 16) + b_row_l, b_chk);
                ldsm_x4(bfr[0][p], base + 2 * TILE_B + ro);
                ldsm_x4(bfr[1][p], base + 3 * TILE_B + ro);
            }
            // 3 passes: (Ah,Bh), (Ah,Bl), (Al,Bh)
#pragma unroll
            for (int ps = 0; ps < 3; ps++) {
                const int ah = (ps == 2), bh = (ps == 1);
#pragma unroll
                for (int mt = 0; mt < 4; mt++)
#pragma unroll
                    for (int nt = 0; nt < 4; nt++)
                        mma16816(acc[mt][nt], af[ah][mt],
                                 &bfr[bh][nt >> 1][(nt & 1) * 2]);
            }
        }
        st = (st == 2) ? 0 : st + 1;
        ls = (ls == 2) ? 0 : ls + 1;
    }

    // ---- epilogue ----
    const int tq = lane >> 2, tr = lane & 3;
#pragma unroll
    for (int nt = 0; nt < 4; nt++) {
        const int n = n0 + wn * 32 + nt * 8 + tr * 2;
        float b0 = 0.f, b1 = 0.f;
        if (HAS_BIAS) { b0 = bias[n]; b1 = bias[n + 1]; }
#pragma unroll
        for (int mt = 0; mt < 4; mt++) {
            const int m = m0 + wm * 64 + mt * 16 + tq;
            float2 o0, o1;
            o0.x = fmaf(alpha, acc[mt][nt][0], b0);
            o0.y = fmaf(alpha, acc[mt][nt][1], b1);
            o1.x = fmaf(alpha, acc[mt][nt][2], b0);
            o1.y = fmaf(alpha, acc[mt][nt][3], b1);
            const long long r0 = cz + (long long)m * ldc + n;
            const long long r1 = cz + (long long)(m + 8) * ldc + n;
            if (WRITE_F32) {
                *(float2*)(C + r0) = o0;
                *(float2*)(C + r1) = o1;
            }
            if (WRITE_SPLIT) {
                bf16 h0, l0, h1, l1;
                split1(o0.x, h0, l0); split1(o0.y, h1, l1);
                *(uint32_t*)(Oh + r0) = pack2(h0, h1);
                *(uint32_t*)(Ol + r0) = pack2(l0, l1);
                split1(o1.x, h0, l0); split1(o1.y, h1, l1);
                *(uint32_t*)(Oh + r1) = pack2(h0, h1);
                *(uint32_t*)(Ol + r1) = pack2(l0, l1);
            }
        }
    }
#undef LOAD_STAGE
}

// ---------------------------------------------------------------------------
// elementwise fp32 -> bf16 hi/lo split
// ---------------------------------------------------------------------------
__global__ __launch_bounds__(256)
void split_kernel(const float* __restrict__ in, bf16* __restrict__ oh,
                  bf16* __restrict__ ol)
{
    const size_t i = ((size_t)blockIdx.x * 256 + threadIdx.x) * 4;
    const float4 v = *(const float4*)(in + i);
    bf16 h0, h1, h2, h3, l0, l1, l2, l3;
    split1(v.x, h0, l0); split1(v.y, h1, l1);
    split1(v.z, h2, l2); split1(v.w, h3, l3);
    *(uint2*)(oh + i) = make_uint2(pack2(h0, h1), pack2(h2, h3));
    *(uint2*)(ol + i) = make_uint2(pack2(l0, l1), pack2(l2, l3));
}

// ---------------------------------------------------------------------------
// fp32 transpose + split:  in [R][C] (row stride ldin) -> oh/ol [C][R]
// (used for the weight matrices)
// ---------------------------------------------------------------------------
__global__ __launch_bounds__(256)
void transpose_split(const float* __restrict__ in, int ldin, long long sIn,
                     bf16* __restrict__ oh, bf16* __restrict__ ol,
                     int R, long long sOut)
{
    __shared__ float t[32][33];
    in += blockIdx.z * sIn;
    oh += blockIdx.z * sOut;
    ol += blockIdx.z * sOut;
    const int c0 = blockIdx.x * 32, r0 = blockIdx.y * 32;
    const int x = threadIdx.x, y = threadIdx.y;
#pragma unroll
    for (int j = 0; j < 32; j += 8)
        t[y + j][x] = in[(long long)(r0 + y + j) * ldin + c0 + x];
    __syncthreads();
#pragma unroll
    for (int j = 0; j < 32; j += 8) {
        const float v = t[x][y + j];
        bf16 h, l;
        split1(v, h, l);
        oh[(long long)(c0 + y + j) * R + r0 + x] = h;
        ol[(long long)(c0 + y + j) * R + r0 + x] = l;
    }
}

// ---------------------------------------------------------------------------
// bf16 dual-plane transpose: inh/inl [R][C-rows of stride ldin] -> oh/ol [C][R]
// (builds V^T hi/lo directly from the qkv bf16 planes — bit-identical to
//  splitting after transpose)
// ---------------------------------------------------------------------------
__global__ __launch_bounds__(256)
void transpose_bf16_2(const bf16* __restrict__ inh, const bf16* __restrict__ inl,
                      int ldin, long long sIn,
                      bf16* __restrict__ oh, bf16* __restrict__ ol,
                      int R, long long sOut)
{
    __shared__ bf16 th[32][33];
    __shared__ bf16 tl[32][33];
    inh += blockIdx.z * sIn;
    inl += blockIdx.z * sIn;
    oh  += blockIdx.z * sOut;
    ol  += blockIdx.z * sOut;
    const int c0 = blockIdx.x * 32, r0 = blockIdx.y * 32;
    const int x = threadIdx.x, y = threadIdx.y;
#pragma unroll
    for (int j = 0; j < 32; j += 8) {
        th[y + j][x] = inh[(long long)(r0 + y + j) * ldin + c0 + x];
        tl[y + j][x] = inl[(long long)(r0 + y + j) * ldin + c0 + x];
    }
    __syncthreads();
#pragma unroll
    for (int j = 0; j < 32; j += 8) {
        oh[(long long)(c0 + y + j) * R + r0 + x] = th[x][y + j];
        ol[(long long)(c0 + y + j) * R + r0 + x] = tl[x][y + j];
    }
}

// ---------------------------------------------------------------------------
// row softmax over S (fp32) -> bf16 hi/lo outputs
// ---------------------------------------------------------------------------
__global__ __launch_bounds__(256)
void softmax_split_kernel(const float* __restrict__ S, bf16* __restrict__ Sh,
                          bf16* __restrict__ Sl)
{
    const size_t ro = (size_t)blockIdx.x * N_;
    const float* p = S + ro;
    const int tid = threadIdx.x;
    const int w = tid >> 5, l = tid & 31;

    float4 v[4];
#pragma unroll
    for (int i = 0; i < 4; i++)
        v[i] = *(const float4*)(p + (size_t)(tid + i * 256) * 4);

    float m = v[0].x;
#pragma unroll
    for (int i = 0; i < 4; i++) {
        m = fmaxf(m, v[i].x); m = fmaxf(m, v[i].y);
        m = fmaxf(m, v[i].z); m = fmaxf(m, v[i].w);
    }
#pragma unroll
    for (int o = 16; o > 0; o >>= 1)
        m = fmaxf(m, __shfl_xor_sync(0xffffffffu, m, o));

    __shared__ float red[8];
    if (l == 0) red[w] = m;
    __syncthreads();
    float bm = red[0];
#pragma unroll
    for (int i = 1; i < 8; i++) bm = fmaxf(bm, red[i]);
    __syncthreads();

    float s = 0.0f;
#pragma unroll
    for (int i = 0; i < 4; i++) {
        v[i].x = expf(v[i].x - bm); s += v[i].x;
        v[i].y = expf(v[i].y - bm); s += v[i].y;
        v[i].z = expf(v[i].z - bm); s += v[i].z;
        v[i].w = expf(v[i].w - bm); s += v[i].w;
    }
#pragma unroll
    for (int o = 16; o > 0; o >>= 1)
        s += __shfl_xor_sync(0xffffffffu, s, o);
    if (l == 0) red[w] = s;
    __syncthreads();
    float tot = red[0];
#pragma unroll
    for (int i = 1; i < 8; i++) tot += red[i];
    const float inv = 1.0f / tot;

#pragma unroll
    for (int i = 0; i < 4; i++) {
        const size_t o = ro + (size_t)(tid + i * 256) * 4;
        bf16 h0, h1, h2, h3, l0, l1, l2, l3;
        split1(v[i].x * inv, h0, l0);
        split1(v[i].y * inv, h1, l1);
        split1(v[i].z * inv, h2, l2);
        split1(v[i].w * inv, h3, l3);
        *(uint2*)(Sh + o) = make_uint2(pack2(h0, h1), pack2(h2, h3));
        *(uint2*)(Sl + o) = make_uint2(pack2(l0, l1), pack2(l2, l3));
    }
}

// ---------------------------------------------------------------------------
extern "C" void kernel_launch(void* const* d_in, const int* in_sizes, int n_in,
                              void* d_out, int out_size)
{
    const float* x     = (const float*)d_in[0];
    const float* w_qkv = (const float*)d_in[1];
    const float* b_qkv = (const float*)d_in[2];
    const float* w_out = (const float*)d_in[3];
    const float* b_out = (const float*)d_in[4];
    float* out = (float*)d_out;

    float *S;
    bf16 *xh, *xl, *qh, *ql, *sh, *sl, *vth, *vtl, *ch, *cl, *wqh, *wql, *woh, *wol;
    cudaGetSymbolAddress((void**)&S,   g_s);
    cudaGetSymbolAddress((void**)&xh,  g_xh);  cudaGetSymbolAddress((void**)&xl,  g_xl);
    cudaGetSymbolAddress((void**)&qh,  g_qh);  cudaGetSymbolAddress((void**)&ql,  g_ql);
    cudaGetSymbolAddress((void**)&sh,  g_sh);  cudaGetSymbolAddress((void**)&sl,  g_sl);
    cudaGetSymbolAddress((void**)&vth, g_vth); cudaGetSymbolAddress((void**)&vtl, g_vtl);
    cudaGetSymbolAddress((void**)&ch,  g_ch);  cudaGetSymbolAddress((void**)&cl,  g_cl);
    cudaGetSymbolAddress((void**)&wqh, g_wqh); cudaGetSymbolAddress((void**)&wql, g_wql);
    cudaGetSymbolAddress((void**)&woh, g_woh); cudaGetSymbolAddress((void**)&wol, g_wol);

    cudaFuncSetAttribute(mma_gemm<true, false, true>,
        cudaFuncAttributeMaxDynamicSharedMemorySize, SMEM_DYN);
    cudaFuncSetAttribute(mma_gemm<false, true, false>,
        cudaFuncAttributeMaxDynamicSharedMemorySize, SMEM_DYN);
    cudaFuncSetAttribute(mma_gemm<false, false, true>,
        cudaFuncAttributeMaxDynamicSharedMemorySize, SMEM_DYN);
    cudaFuncSetAttribute(mma_gemm<true, true, false>,
        cudaFuncAttributeMaxDynamicSharedMemorySize, SMEM_DYN);

    const dim3 blk(256);
    const dim3 tblk(32, 8);

    // operand prep
    split_kernel<<<(B_ * N_ * D_) / 1024, blk>>>(x, xh, xl);
    transpose_split<<<dim3(QKVC / 32, D_ / 32, 1), tblk>>>(
        w_qkv, QKVC, 0, wqh, wql, D_, 0);
    transpose_split<<<dim3(D_ / 32, D_ / 32, 1), tblk>>>(
        w_out, D_, 0, woh, wol, D_, 0);

    // 1) qkv = x @ w_qkv + b_qkv   (bf16 hi/lo split only — no fp32 output)
    mma_gemm<true, false, true><<<dim3(QKVC / 128, (B_ * N_) / 128, 1), blk, SMEM_DYN>>>(
        xh, xl, wqh, wql, b_qkv, nullptr, qh, ql, D_, D_, D_, QKVC, 0, 0, 0, 1.0f);

    // V^T (per batch): bf16 planes of qkv cols [2D..3D) -> [D][N]
    transpose_bf16_2<<<dim3(D_ / 32, N_ / 32, B_), tblk>>>(
        qh + 2 * D_, ql + 2 * D_, QKVC, (long long)N_ * QKVC,
        vth, vtl, N_, (long long)D_ * N_);

    // 2) S = scale * Q @ K^T
    mma_gemm<false, true, false><<<dim3(N_ / 128, N_ / 128, B_), blk, SMEM_DYN>>>(
        qh, ql, qh + D_, ql + D_, nullptr, S, nullptr, nullptr, D_, QKVC, QKVC, N_,
        (long long)N_ * QKVC, (long long)N_ * QKVC, (long long)N_ * N_, SCALE_F);

    // 3) softmax + split
    softmax_split_kernel<<<B_ * N_, blk>>>(S, sh, sl);

    // 4) ctx = S @ V   (hi/lo split only, no fp32 intermediate)
    mma_gemm<false, false, true><<<dim3(D_ / 128, N_ / 128, B_), blk, SMEM_DYN>>>(
        sh, sl, vth, vtl, nullptr, nullptr, ch, cl, N_, N_, N_, D_,
        (long long)N_ * N_, (long long)D_ * N_, (long long)N_ * D_, 1.0f);

    // 5) out = ctx @ w_out + b_out
    mma_gemm<true, true, false><<<dim3(D_ / 128, (B_ * N_) / 128, 1), blk, SMEM_DYN>>>(
        ch, cl, woh, wol, b_out, out, nullptr, nullptr, D_, D_, D_, D_, 0, 0, 0, 1.0f);
}

// round 9
// speedup vs baseline: 1.0509x; 1.0041x over previous
#include <cuda_runtime.h>
#include <cuda_bf16.h>
#include <stdint.h>
#include <math.h>

// ---------------------------------------------------------------------------
// MySelfAttention_V2 (B=4, N=4096, D=768) — mma.sync bf16 hi/lo split (3-pass)
// R9: algebraic flop cut. S = softmax(scale*(Q K^T)) with Q=xWq+bq, K=xWk+bk
//     rewritten as S ~ scale*(y x^T) + c_j  (row-constants dropped; softmax-inv)
//     where Mt = Wk Wq^T, y = x @ Mt^T, c_j = scale*(x_j . (Wk bq)).
//     Removes the Q/K projections: 2304-col qkv GEMM -> two 768-col GEMMs.
// GEMM core: unchanged from R8 (128x128 tile, BK=32, 3-stage cp.async,
//     XOR-swizzled 64B rows, __launch_bounds__(256,2), 128 regs, 2 CTA/SM).
// ---------------------------------------------------------------------------

#define B_   4
#define N_   4096
#define D_   768
#define QKVC 2304
#define SCALE_F 0.03608439182435161f

typedef __nv_bfloat16 bf16;

// ---------------- scratch (static device globals: allocation-guard-safe) ----
__device__ float g_s    [(size_t)B_ * N_ * N_];
__device__ bf16  g_xh   [(size_t)B_ * N_ * D_],  g_xl  [(size_t)B_ * N_ * D_];
__device__ bf16  g_wrh  [(size_t)D_ * QKVC],     g_wrl [(size_t)D_ * QKVC];
__device__ bf16  g_mth  [(size_t)D_ * D_],       g_mtl [(size_t)D_ * D_];
__device__ bf16  g_wvh  [(size_t)D_ * D_],       g_wvl [(size_t)D_ * D_];
__device__ bf16  g_vh   [(size_t)B_ * N_ * D_],  g_vl  [(size_t)B_ * N_ * D_];
__device__ bf16  g_yh   [(size_t)B_ * N_ * D_],  g_yl  [(size_t)B_ * N_ * D_];
__device__ bf16  g_sh   [(size_t)B_ * N_ * N_],  g_sl  [(size_t)B_ * N_ * N_];
__device__ bf16  g_vth  [(size_t)B_ * D_ * N_],  g_vtl [(size_t)B_ * D_ * N_];
__device__ bf16  g_ch   [(size_t)B_ * N_ * D_],  g_cl  [(size_t)B_ * N_ * D_];
__device__ bf16  g_woh  [(size_t)D_ * D_],       g_wol [(size_t)D_ * D_];
__device__ float g_wv   [D_];
__device__ float g_cvec [(size_t)B_ * N_];

// ---------------- PTX helpers ----------------------------------------------
static __device__ __forceinline__ uint32_t smem_u32(const void* p) {
    uint32_t a;
    asm("{ .reg .u64 t; cvta.to.shared.u64 t, %1; cvt.u32.u64 %0, t; }"
        : "=r"(a) : "l"(p));
    return a;
}
static __device__ __forceinline__ void cp_async16(uint32_t saddr, const void* g) {
    asm volatile("cp.async.cg.shared.global [%0], [%1], 16;"
                 :: "r"(saddr), "l"(g) : "memory");
}
static __device__ __forceinline__ void cp_commit() {
    asm volatile("cp.async.commit_group;" ::: "memory");
}
template <int N>
static __device__ __forceinline__ void cp_wait() {
    asm volatile("cp.async.wait_group %0;" :: "n"(N) : "memory");
}
static __device__ __forceinline__ void ldsm_x4(uint32_t* r, uint32_t addr) {
    asm volatile("ldmatrix.sync.aligned.m8n8.x4.shared.b16 {%0,%1,%2,%3}, [%4];"
                 : "=r"(r[0]), "=r"(r[1]), "=r"(r[2]), "=r"(r[3]) : "r"(addr));
}
static __device__ __forceinline__ void mma16816(float* c, const uint32_t* a,
                                                const uint32_t* b) {
    asm volatile(
        "mma.sync.aligned.m16n8k16.row.col.f32.bf16.bf16.f32 "
        "{%0,%1,%2,%3}, {%4,%5,%6,%7}, {%8,%9}, {%0,%1,%2,%3};"
        : "+f"(c[0]), "+f"(c[1]), "+f"(c[2]), "+f"(c[3])
        : "r"(a[0]), "r"(a[1]), "r"(a[2]), "r"(a[3]), "r"(b[0]), "r"(b[1]));
}
static __device__ __forceinline__ void split1(float v, bf16& h, bf16& l) {
    h = __float2bfloat16_rn(v);
    l = __float2bfloat16_rn(v - __bfloat162float(h));
}
static __device__ __forceinline__ uint32_t pack2(bf16 a, bf16 b) {
    return (uint32_t)__bfloat16_as_ushort(a) |
           ((uint32_t)__bfloat16_as_ushort(b) << 16);
}
static __device__ __forceinline__ uint32_t swz(uint32_t row, uint32_t chunk) {
    return row * 64u + (((chunk ^ (row >> 1)) & 3u) << 4);
}

// ---------------------------------------------------------------------------
// GEMM: C[m,n] = alpha * sum_k A[m,k]*B[n,k]  (+bias[n], bias per-z via sBias)
// ---------------------------------------------------------------------------
#define TILE_B 8192                       // 128 rows * 64 B
#define STAGE_B (4 * TILE_B)              // Ah,Al,Bh,Bl
static const int SMEM_DYN = 3 * STAGE_B;  // 98304

template <bool HAS_BIAS, bool WRITE_F32, bool WRITE_SPLIT>
__global__ __launch_bounds__(256, 2)
void mma_gemm(const bf16* __restrict__ Ah, const bf16* __restrict__ Al,
              const bf16* __restrict__ Bh, const bf16* __restrict__ Bl,
              const float* __restrict__ bias, float* __restrict__ C,
              bf16* __restrict__ Oh, bf16* __restrict__ Ol,
              int K, int lda, int ldb, int ldc,
              long long sA, long long sB, long long sC, long long sBias,
              float alpha)
{
    extern __shared__ char smem[];
    const uint32_t sb = smem_u32(smem);

    Ah += blockIdx.z * sA;  Al += blockIdx.z * sA;
    Bh += blockIdx.z * sB;  Bl += blockIdx.z * sB;
    if (HAS_BIAS) bias += blockIdx.z * sBias;
    const long long cz = blockIdx.z * sC;
    const int m0 = blockIdx.y * 128, n0 = blockIdx.x * 128;
    const int tid  = threadIdx.x;
    const int wid  = tid >> 5, lane = tid & 31;
    const int wm   = wid >> 2, wn = wid & 3;   // 2 x 4 warps

    const int cr0 = tid >> 2, cc = tid & 3;
    const uint32_t so0 = swz((uint32_t)cr0, (uint32_t)cc);
    const uint32_t so1 = swz((uint32_t)(cr0 + 64), (uint32_t)cc);

#define LOAD_STAGE(st, k0)                                                      \
    do {                                                                        \
        const uint32_t s0 = sb + (uint32_t)(st) * STAGE_B;                      \
        const long long kof = (long long)(k0) + cc * 8;                         \
        cp_async16(s0 + 0*TILE_B + so0, Ah + (long long)(m0+cr0)    *lda + kof);\
        cp_async16(s0 + 0*TILE_B + so1, Ah + (long long)(m0+cr0+64) *lda + kof);\
        cp_async16(s0 + 1*TILE_B + so0, Al + (long long)(m0+cr0)    *lda + kof);\
        cp_async16(s0 + 1*TILE_B + so1, Al + (long long)(m0+cr0+64) *lda + kof);\
        cp_async16(s0 + 2*TILE_B + so0, Bh + (long long)(n0+cr0)    *ldb + kof);\
        cp_async16(s0 + 2*TILE_B + so1, Bh + (long long)(n0+cr0+64) *ldb + kof);\
        cp_async16(s0 + 3*TILE_B + so0, Bl + (long long)(n0+cr0)    *ldb + kof);\
        cp_async16(s0 + 3*TILE_B + so1, Bl + (long long)(n0+cr0+64) *ldb + kof);\
    } while (0)

    const uint32_t a_row_l = (uint32_t)(lane & 15);
    const uint32_t a_chk_l = (uint32_t)(lane >> 4);
    const uint32_t b_row_l = (uint32_t)((lane & 7) + ((lane >> 4) << 3));
    const uint32_t b_chk_l = (uint32_t)((lane >> 3) & 1);

    float acc[4][4][4];
#pragma unroll
    for (int mt = 0; mt < 4; mt++)
#pragma unroll
        for (int nt = 0; nt < 4; nt++)
#pragma unroll
            for (int r = 0; r < 4; r++) acc[mt][nt][r] = 0.0f;

    const int nch = K / 32;
    LOAD_STAGE(0, 0);
    cp_commit();
    if (nch > 1) LOAD_STAGE(1, 32);
    cp_commit();

    int st = 0, ls = 2;
    for (int ch = 0; ch < nch; ch++) {
        cp_wait<1>();
        __syncthreads();
        if (ch + 2 < nch) LOAD_STAGE(ls, (long long)(ch + 2) * 32);
        cp_commit();

        const uint32_t base = sb + (uint32_t)st * STAGE_B;
#pragma unroll
        for (int kk = 0; kk < 2; kk++) {
            uint32_t af[2][4][4];
            uint32_t bfr[2][2][4];
            const uint32_t a_chk = (uint32_t)(kk * 2) + a_chk_l;
            const uint32_t b_chk = (uint32_t)(kk * 2) + b_chk_l;
#pragma unroll
            for (int mt = 0; mt < 4; mt++) {
                const uint32_t ro = swz((uint32_t)(wm * 64 + mt * 16) + a_row_l, a_chk);
                ldsm_x4(af[0][mt], base + 0 * TILE_B + ro);
                ldsm_x4(af[1][mt], base + 1 * TILE_B + ro);
            }
#pragma unroll
            for (int p = 0; p < 2; p++) {
                const uint32_t ro = swz((uint32_t)(wn * 32 + p * 16) + b_row_l, b_chk);
                ldsm_x4(bfr[0][p], base + 2 * TILE_B + ro);
                ldsm_x4(bfr[1][p], base + 3 * TILE_B + ro);
            }
#pragma unroll
            for (int ps = 0; ps < 3; ps++) {
                const int ah = (ps == 2), bh = (ps == 1);
#pragma unroll
                for (int mt = 0; mt < 4; mt++)
#pragma unroll
                    for (int nt = 0; nt < 4; nt++)
                        mma16816(acc[mt][nt], af[ah][mt],
                                 &bfr[bh][nt >> 1][(nt & 1) * 2]);
            }
        }
        st = (st == 2) ? 0 : st + 1;
        ls = (ls == 2) ? 0 : ls + 1;
    }

    // ---- epilogue ----
    const int tq = lane >> 2, tr = lane & 3;
#pragma unroll
    for (int nt = 0; nt < 4; nt++) {
        const int n = n0 + wn * 32 + nt * 8 + tr * 2;
        float b0 = 0.f, b1 = 0.f;
        if (HAS_BIAS) { b0 = bias[n]; b1 = bias[n + 1]; }
#pragma unroll
        for (int mt = 0; mt < 4; mt++) {
            const int m = m0 + wm * 64 + mt * 16 + tq;
            float2 o0, o1;
            o0.x = fmaf(alpha, acc[mt][nt][0], b0);
            o0.y = fmaf(alpha, acc[mt][nt][1], b1);
            o1.x = fmaf(alpha, acc[mt][nt][2], b0);
            o1.y = fmaf(alpha, acc[mt][nt][3], b1);
            const long long r0 = cz + (long long)m * ldc + n;
            const long long r1 = cz + (long long)(m + 8) * ldc + n;
            if (WRITE_F32) {
                *(float2*)(C + r0) = o0;
                *(float2*)(C + r1) = o1;
            }
            if (WRITE_SPLIT) {
                bf16 h0, l0, h1, l1;
                split1(o0.x, h0, l0); split1(o0.y, h1, l1);
                *(uint32_t*)(Oh + r0) = pack2(h0, h1);
                *(uint32_t*)(Ol + r0) = pack2(l0, l1);
                split1(o1.x, h0, l0); split1(o1.y, h1, l1);
                *(uint32_t*)(Oh + r1) = pack2(h0, h1);
                *(uint32_t*)(Ol + r1) = pack2(l0, l1);
            }
        }
    }
#undef LOAD_STAGE
}

// ---------------------------------------------------------------------------
// elementwise fp32 -> bf16 hi/lo split (count multiple of 1024)
// ---------------------------------------------------------------------------
__global__ __launch_bounds__(256)
void split_kernel(const float* __restrict__ in, bf16* __restrict__ oh,
                  bf16* __restrict__ ol)
{
    const size_t i = ((size_t)blockIdx.x * 256 + threadIdx.x) * 4;
    const float4 v = *(const float4*)(in + i);
    bf16 h0, h1, h2, h3, l0, l1, l2, l3;
    split1(v.x, h0, l0); split1(v.y, h1, l1);
    split1(v.z, h2, l2); split1(v.w, h3, l3);
    *(uint2*)(oh + i) = make_uint2(pack2(h0, h1), pack2(h2, h3));
    *(uint2*)(ol + i) = make_uint2(pack2(l0, l1), pack2(l2, l3));
}

// ---------------------------------------------------------------------------
// fp32 transpose + split:  in [R][C] (row stride ldin) -> oh/ol [C][R]
// ---------------------------------------------------------------------------
__global__ __launch_bounds__(256)
void transpose_split(const float* __restrict__ in, int ldin, long long sIn,
                     bf16* __restrict__ oh, bf16* __restrict__ ol,
                     int R, long long sOut)
{
    __shared__ float t[32][33];
    in += blockIdx.z * sIn;
    oh += blockIdx.z * sOut;
    ol += blockIdx.z * sOut;
    const int c0 = blockIdx.x * 32, r0 = blockIdx.y * 32;
    const int x = threadIdx.x, y = threadIdx.y;
#pragma unroll
    for (int j = 0; j < 32; j += 8)
        t[y + j][x] = in[(long long)(r0 + y + j) * ldin + c0 + x];
    __syncthreads();
#pragma unroll
    for (int j = 0; j < 32; j += 8) {
        const float v = t[x][y + j];
        bf16 h, l;
        split1(v, h, l);
        oh[(long long)(c0 + y + j) * R + r0 + x] = h;
        ol[(long long)(c0 + y + j) * R + r0 + x] = l;
    }
}

// ---------------------------------------------------------------------------
// bf16 dual-plane transpose: inh/inl [R][ldin] -> oh/ol [C][R]
// ---------------------------------------------------------------------------
__global__ __launch_bounds__(256)
void transpose_bf16_2(const bf16* __restrict__ inh, const bf16* __restrict__ inl,
                      int ldin, long long sIn,
                      bf16* __restrict__ oh, bf16* __restrict__ ol,
                      int R, long long sOut)
{
    __shared__ bf16 th[32][33];
    __shared__ bf16 tl[32][33];
    inh += blockIdx.z * sIn;
    inl += blockIdx.z * sIn;
    oh  += blockIdx.z * sOut;
    ol  += blockIdx.z * sOut;
    const int c0 = blockIdx.x * 32, r0 = blockIdx.y * 32;
    const int x = threadIdx.x, y = threadIdx.y;
#pragma unroll
    for (int j = 0; j < 32; j += 8) {
        th[y + j][x] = inh[(long long)(r0 + y + j) * ldin + c0 + x];
        tl[y + j][x] = inl[(long long)(r0 + y + j) * ldin + c0 + x];
    }
    __syncthreads();
#pragma unroll
    for (int j = 0; j < 32; j += 8) {
        oh[(long long)(c0 + y + j) * R + r0 + x] = th[x][y + j];
        ol[(long long)(c0 + y + j) * R + r0 + x] = tl[x][y + j];
    }
}

// ---------------------------------------------------------------------------
// wv[d] = sum_a Wk[d][a] * bq[a]   (Wk = w_qkv cols [D,2D))
// ---------------------------------------------------------------------------
__global__ __launch_bounds__(256)
void wvec_kernel(const float* __restrict__ w_qkv, const float* __restrict__ bq,
                 float* __restrict__ wv)
{
    __shared__ float red[8];
    const int d = blockIdx.x;
    const float* rowp = w_qkv + (size_t)d * QKVC + D_;
    float s = 0.0f;
    for (int a = threadIdx.x; a < D_; a += 256) s += rowp[a] * bq[a];
#pragma unroll
    for (int o = 16; o > 0; o >>= 1) s += __shfl_xor_sync(0xffffffffu, s, o);
    if (!(threadIdx.x & 31)) red[threadIdx.x >> 5] = s;
    __syncthreads();
    if (threadIdx.x == 0) {
        float t = 0.0f;
#pragma unroll
        for (int i = 0; i < 8; i++) t += red[i];
        wv[d] = t;
    }
}

// ---------------------------------------------------------------------------
// cvec[j] = SCALE * sum_d x[j][d] * wv[d]    (j over all B*N rows)
// ---------------------------------------------------------------------------
__global__ __launch_bounds__(256)
void cvec_kernel(const float* __restrict__ x, const float* __restrict__ wv,
                 float* __restrict__ c)
{
    const int row = blockIdx.x * 8 + (threadIdx.x >> 5);
    const int lane = threadIdx.x & 31;
    const float* xr = x + (size_t)row * D_;
    float s = 0.0f;
    for (int d = lane; d < D_; d += 32) s += xr[d] * wv[d];
#pragma unroll
    for (int o = 16; o > 0; o >>= 1) s += __shfl_xor_sync(0xffffffffu, s, o);
    if (lane == 0) c[row] = s * SCALE_F;
}

// ---------------------------------------------------------------------------
// row softmax over S (fp32) -> bf16 hi/lo outputs
// ---------------------------------------------------------------------------
__global__ __launch_bounds__(256)
void softmax_split_kernel(const float* __restrict__ S, bf16* __restrict__ Sh,
                          bf16* __restrict__ Sl)
{
    const size_t ro = (size_t)blockIdx.x * N_;
    const float* p = S + ro;
    const int tid = threadIdx.x;
    const int w = tid >> 5, l = tid & 31;

    float4 v[4];
#pragma unroll
    for (int i = 0; i < 4; i++)
        v[i] = *(const float4*)(p + (size_t)(tid + i * 256) * 4);

    float m = v[0].x;
#pragma unroll
    for (int i = 0; i < 4; i++) {
        m = fmaxf(m, v[i].x); m = fmaxf(m, v[i].y);
        m = fmaxf(m, v[i].z); m = fmaxf(m, v[i].w);
    }
#pragma unroll
    for (int o = 16; o > 0; o >>= 1)
        m = fmaxf(m, __shfl_xor_sync(0xffffffffu, m, o));

    __shared__ float red[8];
    if (l == 0) red[w] = m;
    __syncthreads();
    float bm = red[0];
#pragma unroll
    for (int i = 1; i < 8; i++) bm = fmaxf(bm, red[i]);
    __syncthreads();

    float s = 0.0f;
#pragma unroll
    for (int i = 0; i < 4; i++) {
        v[i].x = expf(v[i].x - bm); s += v[i].x;
        v[i].y = expf(v[i].y - bm); s += v[i].y;
        v[i].z = expf(v[i].z - bm); s += v[i].z;
        v[i].w = expf(v[i].w - bm); s += v[i].w;
    }
#pragma unroll
    for (int o = 16; o > 0; o >>= 1)
        s += __shfl_xor_sync(0xffffffffu, s, o);
    if (l == 0) red[w] = s;
    __syncthreads();
    float tot = red[0];
#pragma unroll
    for (int i = 1; i < 8; i++) tot += red[i];
    const float inv = 1.0f / tot;

#pragma unroll
    for (int i = 0; i < 4; i++) {
        const size_t o = ro + (size_t)(tid + i * 256) * 4;
        bf16 h0, h1, h2, h3, l0, l1, l2, l3;
        split1(v[i].x * inv, h0, l0);
        split1(v[i].y * inv, h1, l1);
        split1(v[i].z * inv, h2, l2);
        split1(v[i].w * inv, h3, l3);
        *(uint2*)(Sh + o) = make_uint2(pack2(h0, h1), pack2(h2, h3));
        *(uint2*)(Sl + o) = make_uint2(pack2(l0, l1), pack2(l2, l3));
    }
}

// ---------------------------------------------------------------------------
extern "C" void kernel_launch(void* const* d_in, const int* in_sizes, int n_in,
                              void* d_out, int out_size)
{
    const float* x     = (const float*)d_in[0];
    const float* w_qkv = (const float*)d_in[1];
    const float* b_qkv = (const float*)d_in[2];
    const float* w_out = (const float*)d_in[3];
    const float* b_out = (const float*)d_in[4];
    float* out = (float*)d_out;

    float *S, *wv, *cvec;
    bf16 *xh, *xl, *wrh, *wrl, *mth, *mtl, *wvh, *wvl, *vh, *vl, *yh, *yl;
    bf16 *sh, *sl, *vth, *vtl, *ch, *cl, *woh, *wol;
    cudaGetSymbolAddress((void**)&S,    g_s);
    cudaGetSymbolAddress((void**)&wv,   g_wv);
    cudaGetSymbolAddress((void**)&cvec, g_cvec);
    cudaGetSymbolAddress((void**)&xh,   g_xh);  cudaGetSymbolAddress((void**)&xl,  g_xl);
    cudaGetSymbolAddress((void**)&wrh,  g_wrh); cudaGetSymbolAddress((void**)&wrl, g_wrl);
    cudaGetSymbolAddress((void**)&mth,  g_mth); cudaGetSymbolAddress((void**)&mtl, g_mtl);
    cudaGetSymbolAddress((void**)&wvh,  g_wvh); cudaGetSymbolAddress((void**)&wvl, g_wvl);
    cudaGetSymbolAddress((void**)&vh,   g_vh);  cudaGetSymbolAddress((void**)&vl,  g_vl);
    cudaGetSymbolAddress((void**)&yh,   g_yh);  cudaGetSymbolAddress((void**)&yl,  g_yl);
    cudaGetSymbolAddress((void**)&sh,   g_sh);  cudaGetSymbolAddress((void**)&sl,  g_sl);
    cudaGetSymbolAddress((void**)&vth,  g_vth); cudaGetSymbolAddress((void**)&vtl, g_vtl);
    cudaGetSymbolAddress((void**)&ch,   g_ch);  cudaGetSymbolAddress((void**)&cl,  g_cl);
    cudaGetSymbolAddress((void**)&woh,  g_woh); cudaGetSymbolAddress((void**)&wol, g_wol);

    cudaFuncSetAttribute(mma_gemm<true, false, true>,
        cudaFuncAttributeMaxDynamicSharedMemorySize, SMEM_DYN);
    cudaFuncSetAttribute(mma_gemm<false, false, true>,
        cudaFuncAttributeMaxDynamicSharedMemorySize, SMEM_DYN);
    cudaFuncSetAttribute(mma_gemm<true, true, false>,
        cudaFuncAttributeMaxDynamicSharedMemorySize, SMEM_DYN);

    const dim3 blk(256);
    const dim3 tblk(32, 8);
    const long long ND = (long long)N_ * D_;
    const long long NN = (long long)N_ * N_;

    // ---- operand prep ----
    split_kernel<<<(B_ * N_ * D_) / 1024, blk>>>(x, xh, xl);
    split_kernel<<<(D_ * QKVC) / 1024, blk>>>(w_qkv, wrh, wrl);   // row-major split
    transpose_split<<<dim3(D_ / 32, D_ / 32, 1), tblk>>>(
        w_qkv + 2 * D_, QKVC, 0, wvh, wvl, D_, 0);                // Wv^T
    transpose_split<<<dim3(D_ / 32, D_ / 32, 1), tblk>>>(
        w_out, D_, 0, woh, wol, D_, 0);                           // Wo^T
    wvec_kernel<<<D_, blk>>>(w_qkv, b_qkv, wv);                   // Wk bq
    cvec_kernel<<<(B_ * N_) / 8, blk>>>(x, wv, cvec);             // scale*(x . wv)

    // Mt = Wk Wq^T  [768x768], split output
    mma_gemm<false, false, true><<<dim3(D_ / 128, D_ / 128, 1), blk, SMEM_DYN>>>(
        wrh + D_, wrl + D_, wrh, wrl, nullptr, nullptr, mth, mtl,
        D_, QKVC, QKVC, D_, 0, 0, 0, 0, 1.0f);

    // V = x @ Wv + bv  (split output)
    mma_gemm<true, false, true><<<dim3(D_ / 128, (B_ * N_) / 128, 1), blk, SMEM_DYN>>>(
        xh, xl, wvh, wvl, b_qkv + 2 * D_, nullptr, vh, vl,
        D_, D_, D_, D_, 0, 0, 0, 0, 1.0f);

    // y = x @ Mt^T  (split output)
    mma_gemm<false, false, true><<<dim3(D_ / 128, (B_ * N_) / 128, 1), blk, SMEM_DYN>>>(
        xh, xl, mth, mtl, nullptr, nullptr, yh, yl,
        D_, D_, D_, D_, 0, 0, 0, 0, 1.0f);

    // V^T per batch
    transpose_bf16_2<<<dim3(D_ / 32, N_ / 32, B_), tblk>>>(
        vh, vl, D_, ND, vth, vtl, N_, (long long)D_ * N_);

    // S = scale*(y x^T) + cvec[j]   (fp32)
    mma_gemm<true, true, false><<<dim3(N_ / 128, N_ / 128, B_), blk, SMEM_DYN>>>(
        yh, yl, xh, xl, cvec, S, nullptr, nullptr,
        D_, D_, D_, N_, ND, ND, NN, N_, SCALE_F);

    // softmax + split
    softmax_split_kernel<<<B_ * N_, blk>>>(S, sh, sl);

    // ctx = P @ V  (split output)
    mma_gemm<false, false, true><<<dim3(D_ / 128, N_ / 128, B_), blk, SMEM_DYN>>>(
        sh, sl, vth, vtl, nullptr, nullptr, ch, cl,
        N_, N_, N_, D_, NN, (long long)D_ * N_, ND, 0, 1.0f);

    // out = ctx @ Wo + bo  (fp32)
    mma_gemm<true, true, false><<<dim3(D_ / 128, (B_ * N_) / 128, 1), blk, SMEM_DYN>>>(
        ch, cl, woh, wol, b_out, out, nullptr, nullptr,
        D_, D_, D_, D_, 0, 0, 0, 0, 1.0f);
}

// round 10
// speedup vs baseline: 1.0825x; 1.0301x over previous
#include <cuda_runtime.h>
#include <cuda_bf16.h>
#include <stdint.h>
#include <math.h>

// ---------------------------------------------------------------------------
// MySelfAttention_V2 (B=4, N=4096, D=768) — mma.sync bf16 hi/lo split (3-pass)
// R10: captured stream fork — V path (Wv^T/Wo^T, V GEMM, V^T) overlaps the
//      Mt/y/S chain inside the CUDA graph. Numerics identical to R9.
// ---------------------------------------------------------------------------

#define B_   4
#define N_   4096
#define D_   768
#define QKVC 2304
#define SCALE_F 0.03608439182435161f

typedef __nv_bfloat16 bf16;

// ---------------- scratch (static device globals: allocation-guard-safe) ----
__device__ float g_s    [(size_t)B_ * N_ * N_];
__device__ bf16  g_xh   [(size_t)B_ * N_ * D_],  g_xl  [(size_t)B_ * N_ * D_];
__device__ bf16  g_wrh  [(size_t)D_ * QKVC],     g_wrl [(size_t)D_ * QKVC];
__device__ bf16  g_mth  [(size_t)D_ * D_],       g_mtl [(size_t)D_ * D_];
__device__ bf16  g_wvh  [(size_t)D_ * D_],       g_wvl [(size_t)D_ * D_];
__device__ bf16  g_vh   [(size_t)B_ * N_ * D_],  g_vl  [(size_t)B_ * N_ * D_];
__device__ bf16  g_yh   [(size_t)B_ * N_ * D_],  g_yl  [(size_t)B_ * N_ * D_];
__device__ bf16  g_sh   [(size_t)B_ * N_ * N_],  g_sl  [(size_t)B_ * N_ * N_];
__device__ bf16  g_vth  [(size_t)B_ * D_ * N_],  g_vtl [(size_t)B_ * D_ * N_];
__device__ bf16  g_ch   [(size_t)B_ * N_ * D_],  g_cl  [(size_t)B_ * N_ * D_];
__device__ bf16  g_woh  [(size_t)D_ * D_],       g_wol [(size_t)D_ * D_];
__device__ float g_wv   [D_];
__device__ float g_cvec [(size_t)B_ * N_];

// ---------------- PTX helpers ----------------------------------------------
static __device__ __forceinline__ uint32_t smem_u32(const void* p) {
    uint32_t a;
    asm("{ .reg .u64 t; cvta.to.shared.u64 t, %1; cvt.u32.u64 %0, t; }"
        : "=r"(a) : "l"(p));
    return a;
}
static __device__ __forceinline__ void cp_async16(uint32_t saddr, const void* g) {
    asm volatile("cp.async.cg.shared.global [%0], [%1], 16;"
                 :: "r"(saddr), "l"(g) : "memory");
}
static __device__ __forceinline__ void cp_commit() {
    asm volatile("cp.async.commit_group;" ::: "memory");
}
template <int N>
static __device__ __forceinline__ void cp_wait() {
    asm volatile("cp.async.wait_group %0;" :: "n"(N) : "memory");
}
static __device__ __forceinline__ void ldsm_x4(uint32_t* r, uint32_t addr) {
    asm volatile("ldmatrix.sync.aligned.m8n8.x4.shared.b16 {%0,%1,%2,%3}, [%4];"
                 : "=r"(r[0]), "=r"(r[1]), "=r"(r[2]), "=r"(r[3]) : "r"(addr));
}
static __device__ __forceinline__ void mma16816(float* c, const uint32_t* a,
                                                const uint32_t* b) {
    asm volatile(
        "mma.sync.aligned.m16n8k16.row.col.f32.bf16.bf16.f32 "
        "{%0,%1,%2,%3}, {%4,%5,%6,%7}, {%8,%9}, {%0,%1,%2,%3};"
        : "+f"(c[0]), "+f"(c[1]), "+f"(c[2]), "+f"(c[3])
        : "r"(a[0]), "r"(a[1]), "r"(a[2]), "r"(a[3]), "r"(b[0]), "r"(b[1]));
}
static __device__ __forceinline__ void split1(float v, bf16& h, bf16& l) {
    h = __float2bfloat16_rn(v);
    l = __float2bfloat16_rn(v - __bfloat162float(h));
}
static __device__ __forceinline__ uint32_t pack2(bf16 a, bf16 b) {
    return (uint32_t)__bfloat16_as_ushort(a) |
           ((uint32_t)__bfloat16_as_ushort(b) << 16);
}
static __device__ __forceinline__ uint32_t swz(uint32_t row, uint32_t chunk) {
    return row * 64u + (((chunk ^ (row >> 1)) & 3u) << 4);
}

// ---------------------------------------------------------------------------
// GEMM: C[m,n] = alpha * sum_k A[m,k]*B[n,k]  (+bias[n], bias per-z via sBias)
// ---------------------------------------------------------------------------
#define TILE_B 8192                       // 128 rows * 64 B
#define STAGE_B (4 * TILE_B)              // Ah,Al,Bh,Bl
static const int SMEM_DYN = 3 * STAGE_B;  // 98304

template <bool HAS_BIAS, bool WRITE_F32, bool WRITE_SPLIT>
__global__ __launch_bounds__(256, 2)
void mma_gemm(const bf16* __restrict__ Ah, const bf16* __restrict__ Al,
              const bf16* __restrict__ Bh, const bf16* __restrict__ Bl,
              const float* __restrict__ bias, float* __restrict__ C,
              bf16* __restrict__ Oh, bf16* __restrict__ Ol,
              int K, int lda, int ldb, int ldc,
              long long sA, long long sB, long long sC, long long sBias,
              float alpha)
{
    extern __shared__ char smem[];
    const uint32_t sb = smem_u32(smem);

    Ah += blockIdx.z * sA;  Al += blockIdx.z * sA;
    Bh += blockIdx.z * sB;  Bl += blockIdx.z * sB;
    if (HAS_BIAS) bias += blockIdx.z * sBias;
    const long long cz = blockIdx.z * sC;
    const int m0 = blockIdx.y * 128, n0 = blockIdx.x * 128;
    const int tid  = threadIdx.x;
    const int wid  = tid >> 5, lane = tid & 31;
    const int wm   = wid >> 2, wn = wid & 3;   // 2 x 4 warps

    const int cr0 = tid >> 2, cc = tid & 3;
    const uint32_t so0 = swz((uint32_t)cr0, (uint32_t)cc);
    const uint32_t so1 = swz((uint32_t)(cr0 + 64), (uint32_t)cc);

#define LOAD_STAGE(st, k0)                                                      \
    do {                                                                        \
        const uint32_t s0 = sb + (uint32_t)(st) * STAGE_B;                      \
        const long long kof = (long long)(k0) + cc * 8;                         \
        cp_async16(s0 + 0*TILE_B + so0, Ah + (long long)(m0+cr0)    *lda + kof);\
        cp_async16(s0 + 0*TILE_B + so1, Ah + (long long)(m0+cr0+64) *lda + kof);\
        cp_async16(s0 + 1*TILE_B + so0, Al + (long long)(m0+cr0)    *lda + kof);\
        cp_async16(s0 + 1*TILE_B + so1, Al + (long long)(m0+cr0+64) *lda + kof);\
        cp_async16(s0 + 2*TILE_B + so0, Bh + (long long)(n0+cr0)    *ldb + kof);\
        cp_async16(s0 + 2*TILE_B + so1, Bh + (long long)(n0+cr0+64) *ldb + kof);\
        cp_async16(s0 + 3*TILE_B + so0, Bl + (long long)(n0+cr0)    *ldb + kof);\
        cp_async16(s0 + 3*TILE_B + so1, Bl + (long long)(n0+cr0+64) *ldb + kof);\
    } while (0)

    const uint32_t a_row_l = (uint32_t)(lane & 15);
    const uint32_t a_chk_l = (uint32_t)(lane >> 4);
    const uint32_t b_row_l = (uint32_t)((lane & 7) + ((lane >> 4) << 3));
    const uint32_t b_chk_l = (uint32_t)((lane >> 3) & 1);

    float acc[4][4][4];
#pragma unroll
    for (int mt = 0; mt < 4; mt++)
#pragma unroll
        for (int nt = 0; nt < 4; nt++)
#pragma unroll
            for (int r = 0; r < 4; r++) acc[mt][nt][r] = 0.0f;

    const int nch = K / 32;
    LOAD_STAGE(0, 0);
    cp_commit();
    if (nch > 1) LOAD_STAGE(1, 32);
    cp_commit();

    int st = 0, ls = 2;
    for (int ch = 0; ch < nch; ch++) {
        cp_wait<1>();
        __syncthreads();
        if (ch + 2 < nch) LOAD_STAGE(ls, (long long)(ch + 2) * 32);
        cp_commit();

        const uint32_t base = sb + (uint32_t)st * STAGE_B;
#pragma unroll
        for (int kk = 0; kk < 2; kk++) {
            uint32_t af[2][4][4];
            uint32_t bfr[2][2][4];
            const uint32_t a_chk = (uint32_t)(kk * 2) + a_chk_l;
            const uint32_t b_chk = (uint32_t)(kk * 2) + b_chk_l;
#pragma unroll
            for (int mt = 0; mt < 4; mt++) {
                const uint32_t ro = swz((uint32_t)(wm * 64 + mt * 16) + a_row_l, a_chk);
                ldsm_x4(af[0][mt], base + 0 * TILE_B + ro);
                ldsm_x4(af[1][mt], base + 1 * TILE_B + ro);
            }
#pragma unroll
            for (int p = 0; p < 2; p++) {
                const uint32_t ro = swz((uint32_t)(wn * 32 + p * 16) + b_row_l, b_chk);
                ldsm_x4(bfr[0][p], base + 2 * TILE_B + ro);
                ldsm_x4(bfr[1][p], base + 3 * TILE_B + ro);
            }
#pragma unroll
            for (int ps = 0; ps < 3; ps++) {
                const int ah = (ps == 2), bh = (ps == 1);
#pragma unroll
                for (int mt = 0; mt < 4; mt++)
#pragma unroll
                    for (int nt = 0; nt < 4; nt++)
                        mma16816(acc[mt][nt], af[ah][mt],
                                 &bfr[bh][nt >> 1][(nt & 1) * 2]);
            }
        }
        st = (st == 2) ? 0 : st + 1;
        ls = (ls == 2) ? 0 : ls + 1;
    }

    // ---- epilogue ----
    const int tq = lane >> 2, tr = lane & 3;
#pragma unroll
    for (int nt = 0; nt < 4; nt++) {
        const int n = n0 + wn * 32 + nt * 8 + tr * 2;
        float b0 = 0.f, b1 = 0.f;
        if (HAS_BIAS) { b0 = bias[n]; b1 = bias[n + 1]; }
#pragma unroll
        for (int mt = 0; mt < 4; mt++) {
            const int m = m0 + wm * 64 + mt * 16 + tq;
            float2 o0, o1;
            o0.x = fmaf(alpha, acc[mt][nt][0], b0);
            o0.y = fmaf(alpha, acc[mt][nt][1], b1);
            o1.x = fmaf(alpha, acc[mt][nt][2], b0);
            o1.y = fmaf(alpha, acc[mt][nt][3], b1);
            const long long r0 = cz + (long long)m * ldc + n;
            const long long r1 = cz + (long long)(m + 8) * ldc + n;
            if (WRITE_F32) {
                *(float2*)(C + r0) = o0;
                *(float2*)(C + r1) = o1;
            }
            if (WRITE_SPLIT) {
                bf16 h0, l0, h1, l1;
                split1(o0.x, h0, l0); split1(o0.y, h1, l1);
                *(uint32_t*)(Oh + r0) = pack2(h0, h1);
                *(uint32_t*)(Ol + r0) = pack2(l0, l1);
                split1(o1.x, h0, l0); split1(o1.y, h1, l1);
                *(uint32_t*)(Oh + r1) = pack2(h0, h1);
                *(uint32_t*)(Ol + r1) = pack2(l0, l1);
            }
        }
    }
#undef LOAD_STAGE
}

// ---------------------------------------------------------------------------
__global__ __launch_bounds__(256)
void split_kernel(const float* __restrict__ in, bf16* __restrict__ oh,
                  bf16* __restrict__ ol)
{
    const size_t i = ((size_t)blockIdx.x * 256 + threadIdx.x) * 4;
    const float4 v = *(const float4*)(in + i);
    bf16 h0, h1, h2, h3, l0, l1, l2, l3;
    split1(v.x, h0, l0); split1(v.y, h1, l1);
    split1(v.z, h2, l2); split1(v.w, h3, l3);
    *(uint2*)(oh + i) = make_uint2(pack2(h0, h1), pack2(h2, h3));
    *(uint2*)(ol + i) = make_uint2(pack2(l0, l1), pack2(l2, l3));
}

// ---------------------------------------------------------------------------
__global__ __launch_bounds__(256)
void transpose_split(const float* __restrict__ in, int ldin, long long sIn,
                     bf16* __restrict__ oh, bf16* __restrict__ ol,
                     int R, long long sOut)
{
    __shared__ float t[32][33];
    in += blockIdx.z * sIn;
    oh += blockIdx.z * sOut;
    ol += blockIdx.z * sOut;
    const int c0 = blockIdx.x * 32, r0 = blockIdx.y * 32;
    const int x = threadIdx.x, y = threadIdx.y;
#pragma unroll
    for (int j = 0; j < 32; j += 8)
        t[y + j][x] = in[(long long)(r0 + y + j) * ldin + c0 + x];
    __syncthreads();
#pragma unroll
    for (int j = 0; j < 32; j += 8) {
        const float v = t[x][y + j];
        bf16 h, l;
        split1(v, h, l);
        oh[(long long)(c0 + y + j) * R + r0 + x] = h;
        ol[(long long)(c0 + y + j) * R + r0 + x] = l;
    }
}

// ---------------------------------------------------------------------------
__global__ __launch_bounds__(256)
void transpose_bf16_2(const bf16* __restrict__ inh, const bf16* __restrict__ inl,
                      int ldin, long long sIn,
                      bf16* __restrict__ oh, bf16* __restrict__ ol,
                      int R, long long sOut)
{
    __shared__ bf16 th[32][33];
    __shared__ bf16 tl[32][33];
    inh += blockIdx.z * sIn;
    inl += blockIdx.z * sIn;
    oh  += blockIdx.z * sOut;
    ol  += blockIdx.z * sOut;
    const int c0 = blockIdx.x * 32, r0 = blockIdx.y * 32;
    const int x = threadIdx.x, y = threadIdx.y;
#pragma unroll
    for (int j = 0; j < 32; j += 8) {
        th[y + j][x] = inh[(long long)(r0 + y + j) * ldin + c0 + x];
        tl[y + j][x] = inl[(long long)(r0 + y + j) * ldin + c0 + x];
    }
    __syncthreads();
#pragma unroll
    for (int j = 0; j < 32; j += 8) {
        oh[(long long)(c0 + y + j) * R + r0 + x] = th[x][y + j];
        ol[(long long)(c0 + y + j) * R + r0 + x] = tl[x][y + j];
    }
}

// ---------------------------------------------------------------------------
__global__ __launch_bounds__(256)
void wvec_kernel(const float* __restrict__ w_qkv, const float* __restrict__ bq,
                 float* __restrict__ wv)
{
    __shared__ float red[8];
    const int d = blockIdx.x;
    const float* rowp = w_qkv + (size_t)d * QKVC + D_;
    float s = 0.0f;
    for (int a = threadIdx.x; a < D_; a += 256) s += rowp[a] * bq[a];
#pragma unroll
    for (int o = 16; o > 0; o >>= 1) s += __shfl_xor_sync(0xffffffffu, s, o);
    if (!(threadIdx.x & 31)) red[threadIdx.x >> 5] = s;
    __syncthreads();
    if (threadIdx.x == 0) {
        float t = 0.0f;
#pragma unroll
        for (int i = 0; i < 8; i++) t += red[i];
        wv[d] = t;
    }
}

// ---------------------------------------------------------------------------
__global__ __launch_bounds__(256)
void cvec_kernel(const float* __restrict__ x, const float* __restrict__ wv,
                 float* __restrict__ c)
{
    const int row = blockIdx.x * 8 + (threadIdx.x >> 5);
    const int lane = threadIdx.x & 31;
    const float* xr = x + (size_t)row * D_;
    float s = 0.0f;
    for (int d = lane; d < D_; d += 32) s += xr[d] * wv[d];
#pragma unroll
    for (int o = 16; o > 0; o >>= 1) s += __shfl_xor_sync(0xffffffffu, s, o);
    if (lane == 0) c[row] = s * SCALE_F;
}

// ---------------------------------------------------------------------------
__global__ __launch_bounds__(256)
void softmax_split_kernel(const float* __restrict__ S, bf16* __restrict__ Sh,
                          bf16* __restrict__ Sl)
{
    const size_t ro = (size_t)blockIdx.x * N_;
    const float* p = S + ro;
    const int tid = threadIdx.x;
    const int w = tid >> 5, l = tid & 31;

    float4 v[4];
#pragma unroll
    for (int i = 0; i < 4; i++)
        v[i] = *(const float4*)(p + (size_t)(tid + i * 256) * 4);

    float m = v[0].x;
#pragma unroll
    for (int i = 0; i < 4; i++) {
        m = fmaxf(m, v[i].x); m = fmaxf(m, v[i].y);
        m = fmaxf(m, v[i].z); m = fmaxf(m, v[i].w);
    }
#pragma unroll
    for (int o = 16; o > 0; o >>= 1)
        m = fmaxf(m, __shfl_xor_sync(0xffffffffu, m, o));

    __shared__ float red[8];
    if (l == 0) red[w] = m;
    __syncthreads();
    float bm = red[0];
#pragma unroll
    for (int i = 1; i < 8; i++) bm = fmaxf(bm, red[i]);
    __syncthreads();

    float s = 0.0f;
#pragma unroll
    for (int i = 0; i < 4; i++) {
        v[i].x = expf(v[i].x - bm); s += v[i].x;
        v[i].y = expf(v[i].y - bm); s += v[i].y;
        v[i].z = expf(v[i].z - bm); s += v[i].z;
        v[i].w = expf(v[i].w - bm); s += v[i].w;
    }
#pragma unroll
    for (int o = 16; o > 0; o >>= 1)
        s += __shfl_xor_sync(0xffffffffu, s, o);
    if (l == 0) red[w] = s;
    __syncthreads();
    float tot = red[0];
#pragma unroll
    for (int i = 1; i < 8; i++) tot += red[i];
    const float inv = 1.0f / tot;

#pragma unroll
    for (int i = 0; i < 4; i++) {
        const size_t o = ro + (size_t)(tid + i * 256) * 4;
        bf16 h0, h1, h2, h3, l0, l1, l2, l3;
        split1(v[i].x * inv, h0, l0);
        split1(v[i].y * inv, h1, l1);
        split1(v[i].z * inv, h2, l2);
        split1(v[i].w * inv, h3, l3);
        *(uint2*)(Sh + o) = make_uint2(pack2(h0, h1), pack2(h2, h3));
        *(uint2*)(Sl + o) = make_uint2(pack2(l0, l1), pack2(l2, l3));
    }
}

// ---------------------------------------------------------------------------
extern "C" void kernel_launch(void* const* d_in, const int* in_sizes, int n_in,
                              void* d_out, int out_size)
{
    const float* x     = (const float*)d_in[0];
    const float* w_qkv = (const float*)d_in[1];
    const float* b_qkv = (const float*)d_in[2];
    const float* w_out = (const float*)d_in[3];
    const float* b_out = (const float*)d_in[4];
    float* out = (float*)d_out;

    float *S, *wv, *cvec;
    bf16 *xh, *xl, *wrh, *wrl, *mth, *mtl, *wvh, *wvl, *vh, *vl, *yh, *yl;
    bf16 *sh, *sl, *vth, *vtl, *ch, *cl, *woh, *wol;
    cudaGetSymbolAddress((void**)&S,    g_s);
    cudaGetSymbolAddress((void**)&wv,   g_wv);
    cudaGetSymbolAddress((void**)&cvec, g_cvec);
    cudaGetSymbolAddress((void**)&xh,   g_xh);  cudaGetSymbolAddress((void**)&xl,  g_xl);
    cudaGetSymbolAddress((void**)&wrh,  g_wrh); cudaGetSymbolAddress((void**)&wrl, g_wrl);
    cudaGetSymbolAddress((void**)&mth,  g_mth); cudaGetSymbolAddress((void**)&mtl, g_mtl);
    cudaGetSymbolAddress((void**)&wvh,  g_wvh); cudaGetSymbolAddress((void**)&wvl, g_wvl);
    cudaGetSymbolAddress((void**)&vh,   g_vh);  cudaGetSymbolAddress((void**)&vl,  g_vl);
    cudaGetSymbolAddress((void**)&yh,   g_yh);  cudaGetSymbolAddress((void**)&yl,  g_yl);
    cudaGetSymbolAddress((void**)&sh,   g_sh);  cudaGetSymbolAddress((void**)&sl,  g_sl);
    cudaGetSymbolAddress((void**)&vth,  g_vth); cudaGetSymbolAddress((void**)&vtl, g_vtl);
    cudaGetSymbolAddress((void**)&ch,   g_ch);  cudaGetSymbolAddress((void**)&cl,  g_cl);
    cudaGetSymbolAddress((void**)&woh,  g_woh); cudaGetSymbolAddress((void**)&wol, g_wol);

    cudaFuncSetAttribute(mma_gemm<true, false, true>,
        cudaFuncAttributeMaxDynamicSharedMemorySize, SMEM_DYN);
    cudaFuncSetAttribute(mma_gemm<false, false, true>,
        cudaFuncAttributeMaxDynamicSharedMemorySize, SMEM_DYN);
    cudaFuncSetAttribute(mma_gemm<true, true, false>,
        cudaFuncAttributeMaxDynamicSharedMemorySize, SMEM_DYN);

    // side stream + fork/join events, created once (host objects; first call
    // happens during the un-captured correctness run)
    static cudaStream_t s1 = nullptr;
    static cudaEvent_t eRoot = nullptr, eX = nullptr, eV = nullptr;
    if (!s1) {
        cudaStreamCreateWithFlags(&s1, cudaStreamNonBlocking);
        cudaEventCreateWithFlags(&eRoot, cudaEventDisableTiming);
        cudaEventCreateWithFlags(&eX,    cudaEventDisableTiming);
        cudaEventCreateWithFlags(&eV,    cudaEventDisableTiming);
    }

    const dim3 blk(256);
    const dim3 tblk(32, 8);
    const long long ND = (long long)N_ * D_;
    const long long NN = (long long)N_ * N_;

    // ---- fork: root s1 into the capture ----
    cudaEventRecord(eRoot, 0);
    cudaStreamWaitEvent(s1, eRoot, 0);

    // s1: weight transposes (depend only on inputs)
    transpose_split<<<dim3(D_ / 32, D_ / 32, 1), tblk, 0, s1>>>(
        w_qkv + 2 * D_, QKVC, 0, wvh, wvl, D_, 0);                // Wv^T
    transpose_split<<<dim3(D_ / 32, D_ / 32, 1), tblk, 0, s1>>>(
        w_out, D_, 0, woh, wol, D_, 0);                           // Wo^T

    // main: x split, weight row split, bias vectors
    split_kernel<<<(B_ * N_ * D_) / 1024, blk>>>(x, xh, xl);
    cudaEventRecord(eX, 0);
    split_kernel<<<(D_ * QKVC) / 1024, blk>>>(w_qkv, wrh, wrl);
    wvec_kernel<<<D_, blk>>>(w_qkv, b_qkv, wv);
    cvec_kernel<<<(B_ * N_) / 8, blk>>>(x, wv, cvec);

    // s1: V path (needs xh/xl)
    cudaStreamWaitEvent(s1, eX, 0);
    mma_gemm<true, false, true><<<dim3(D_ / 128, (B_ * N_) / 128, 1), blk, SMEM_DYN, s1>>>(
        xh, xl, wvh, wvl, b_qkv + 2 * D_, nullptr, vh, vl,
        D_, D_, D_, D_, 0, 0, 0, 0, 1.0f);
    transpose_bf16_2<<<dim3(D_ / 32, N_ / 32, B_), tblk, 0, s1>>>(
        vh, vl, D_, ND, vth, vtl, N_, (long long)D_ * N_);
    cudaEventRecord(eV, s1);

    // main: Mt = Wk Wq^T
    mma_gemm<false, false, true><<<dim3(D_ / 128, D_ / 128, 1), blk, SMEM_DYN>>>(
        wrh + D_, wrl + D_, wrh, wrl, nullptr, nullptr, mth, mtl,
        D_, QKVC, QKVC, D_, 0, 0, 0, 0, 1.0f);

    // main: y = x @ Mt^T
    mma_gemm<false, false, true><<<dim3(D_ / 128, (B_ * N_) / 128, 1), blk, SMEM_DYN>>>(
        xh, xl, mth, mtl, nullptr, nullptr, yh, yl,
        D_, D_, D_, D_, 0, 0, 0, 0, 1.0f);

    // main: S = scale*(y x^T) + cvec[j]
    mma_gemm<true, true, false><<<dim3(N_ / 128, N_ / 128, B_), blk, SMEM_DYN>>>(
        yh, yl, xh, xl, cvec, S, nullptr, nullptr,
        D_, D_, D_, N_, ND, ND, NN, N_, SCALE_F);

    // main: softmax + split
    softmax_split_kernel<<<B_ * N_, blk>>>(S, sh, sl);

    // ---- join: PV needs V^T ----
    cudaStreamWaitEvent(0, eV, 0);

    // main: ctx = P @ V
    mma_gemm<false, false, true><<<dim3(D_ / 128, N_ / 128, B_), blk, SMEM_DYN>>>(
        sh, sl, vth, vtl, nullptr, nullptr, ch, cl,
        N_, N_, N_, D_, NN, (long long)D_ * N_, ND, 0, 1.0f);

    // main: out = ctx @ Wo + bo
    mma_gemm<true, true, false><<<dim3(D_ / 128, (B_ * N_) / 128, 1), blk, SMEM_DYN>>>(
        ch, cl, woh, wol, b_out, out, nullptr, nullptr,
        D_, D_, D_, D_, 0, 0, 0, 0, 1.0f);
}

// round 12
// speedup vs baseline: 1.1084x; 1.0239x over previous
#include <cuda_runtime.h>
#include <cuda_bf16.h>
#include <stdint.h>
#include <math.h>

// ---------------------------------------------------------------------------
// MySelfAttention_V2 (B=4, N=4096, D=768) — mma.sync bf16 hi/lo split (3-pass)
// R12: per-batch chain pipelining on TWO streams only (R11's 4 extra streams
//      tripped the allocation guard at 512KB/stream; R10's 1-stream footprint
//      is known-legal). Batches 0,2 on capture stream; 1,3 on sv after the
//      V path. Numerics identical to R9/R10.
// ---------------------------------------------------------------------------

#define B_   4
#define N_   4096
#define D_   768
#define QKVC 2304
#define SCALE_F 0.03608439182435161f

typedef __nv_bfloat16 bf16;

// ---------------- scratch (static device globals: allocation-guard-safe) ----
__device__ float g_s    [(size_t)B_ * N_ * N_];
__device__ bf16  g_xh   [(size_t)B_ * N_ * D_],  g_xl  [(size_t)B_ * N_ * D_];
__device__ bf16  g_wrh  [(size_t)D_ * QKVC],     g_wrl [(size_t)D_ * QKVC];
__device__ bf16  g_mth  [(size_t)D_ * D_],       g_mtl [(size_t)D_ * D_];
__device__ bf16  g_wvh  [(size_t)D_ * D_],       g_wvl [(size_t)D_ * D_];
__device__ bf16  g_vh   [(size_t)B_ * N_ * D_],  g_vl  [(size_t)B_ * N_ * D_];
__device__ bf16  g_yh   [(size_t)B_ * N_ * D_],  g_yl  [(size_t)B_ * N_ * D_];
__device__ bf16  g_sh   [(size_t)B_ * N_ * N_],  g_sl  [(size_t)B_ * N_ * N_];
__device__ bf16  g_vth  [(size_t)B_ * D_ * N_],  g_vtl [(size_t)B_ * D_ * N_];
__device__ bf16  g_ch   [(size_t)B_ * N_ * D_],  g_cl  [(size_t)B_ * N_ * D_];
__device__ bf16  g_woh  [(size_t)D_ * D_],       g_wol [(size_t)D_ * D_];
__device__ float g_wv   [D_];
__device__ float g_cvec [(size_t)B_ * N_];

// ---------------- PTX helpers ----------------------------------------------
static __device__ __forceinline__ uint32_t smem_u32(const void* p) {
    uint32_t a;
    asm("{ .reg .u64 t; cvta.to.shared.u64 t, %1; cvt.u32.u64 %0, t; }"
        : "=r"(a) : "l"(p));
    return a;
}
static __device__ __forceinline__ void cp_async16(uint32_t saddr, const void* g) {
    asm volatile("cp.async.cg.shared.global [%0], [%1], 16;"
                 :: "r"(saddr), "l"(g) : "memory");
}
static __device__ __forceinline__ void cp_commit() {
    asm volatile("cp.async.commit_group;" ::: "memory");
}
template <int N>
static __device__ __forceinline__ void cp_wait() {
    asm volatile("cp.async.wait_group %0;" :: "n"(N) : "memory");
}
static __device__ __forceinline__ void ldsm_x4(uint32_t* r, uint32_t addr) {
    asm volatile("ldmatrix.sync.aligned.m8n8.x4.shared.b16 {%0,%1,%2,%3}, [%4];"
                 : "=r"(r[0]), "=r"(r[1]), "=r"(r[2]), "=r"(r[3]) : "r"(addr));
}
static __device__ __forceinline__ void mma16816(float* c, const uint32_t* a,
                                                const uint32_t* b) {
    asm volatile(
        "mma.sync.aligned.m16n8k16.row.col.f32.bf16.bf16.f32 "
        "{%0,%1,%2,%3}, {%4,%5,%6,%7}, {%8,%9}, {%0,%1,%2,%3};"
        : "+f"(c[0]), "+f"(c[1]), "+f"(c[2]), "+f"(c[3])
        : "r"(a[0]), "r"(a[1]), "r"(a[2]), "r"(a[3]), "r"(b[0]), "r"(b[1]));
}
static __device__ __forceinline__ void split1(float v, bf16& h, bf16& l) {
    h = __float2bfloat16_rn(v);
    l = __float2bfloat16_rn(v - __bfloat162float(h));
}
static __device__ __forceinline__ uint32_t pack2(bf16 a, bf16 b) {
    return (uint32_t)__bfloat16_as_ushort(a) |
           ((uint32_t)__bfloat16_as_ushort(b) << 16);
}
static __device__ __forceinline__ uint32_t swz(uint32_t row, uint32_t chunk) {
    return row * 64u + (((chunk ^ (row >> 1)) & 3u) << 4);
}

// ---------------------------------------------------------------------------
// GEMM: C[m,n] = alpha * sum_k A[m,k]*B[n,k]  (+bias[n], bias per-z via sBias)
// ---------------------------------------------------------------------------
#define TILE_B 8192                       // 128 rows * 64 B
#define STAGE_B (4 * TILE_B)              // Ah,Al,Bh,Bl
static const int SMEM_DYN = 3 * STAGE_B;  // 98304

template <bool HAS_BIAS, bool WRITE_F32, bool WRITE_SPLIT>
__global__ __launch_bounds__(256, 2)
void mma_gemm(const bf16* __restrict__ Ah, const bf16* __restrict__ Al,
              const bf16* __restrict__ Bh, const bf16* __restrict__ Bl,
              const float* __restrict__ bias, float* __restrict__ C,
              bf16* __restrict__ Oh, bf16* __restrict__ Ol,
              int K, int lda, int ldb, int ldc,
              long long sA, long long sB, long long sC, long long sBias,
              float alpha)
{
    extern __shared__ char smem[];
    const uint32_t sb = smem_u32(smem);

    Ah += blockIdx.z * sA;  Al += blockIdx.z * sA;
    Bh += blockIdx.z * sB;  Bl += blockIdx.z * sB;
    if (HAS_BIAS) bias += blockIdx.z * sBias;
    const long long cz = blockIdx.z * sC;
    const int m0 = blockIdx.y * 128, n0 = blockIdx.x * 128;
    const int tid  = threadIdx.x;
    const int wid  = tid >> 5, lane = tid & 31;
    const int wm   = wid >> 2, wn = wid & 3;   // 2 x 4 warps

    const int cr0 = tid >> 2, cc = tid & 3;
    const uint32_t so0 = swz((uint32_t)cr0, (uint32_t)cc);
    const uint32_t so1 = swz((uint32_t)(cr0 + 64), (uint32_t)cc);

#define LOAD_STAGE(st, k0)                                                      \
    do {                                                                        \
        const uint32_t s0 = sb + (uint32_t)(st) * STAGE_B;                      \
        const long long kof = (long long)(k0) + cc * 8;                         \
        cp_async16(s0 + 0*TILE_B + so0, Ah + (long long)(m0+cr0)    *lda + kof);\
        cp_async16(s0 + 0*TILE_B + so1, Ah + (long long)(m0+cr0+64) *lda + kof);\
        cp_async16(s0 + 1*TILE_B + so0, Al + (long long)(m0+cr0)    *lda + kof);\
        cp_async16(s0 + 1*TILE_B + so1, Al + (long long)(m0+cr0+64) *lda + kof);\
        cp_async16(s0 + 2*TILE_B + so0, Bh + (long long)(n0+cr0)    *ldb + kof);\
        cp_async16(s0 + 2*TILE_B + so1, Bh + (long long)(n0+cr0+64) *ldb + kof);\
        cp_async16(s0 + 3*TILE_B + so0, Bl + (long long)(n0+cr0)    *ldb + kof);\
        cp_async16(s0 + 3*TILE_B + so1, Bl + (long long)(n0+cr0+64) *ldb + kof);\
    } while (0)

    const uint32_t a_row_l = (uint32_t)(lane & 15);
    const uint32_t a_chk_l = (uint32_t)(lane >> 4);
    const uint32_t b_row_l = (uint32_t)((lane & 7) + ((lane >> 4) << 3));
    const uint32_t b_chk_l = (uint32_t)((lane >> 3) & 1);

    float acc[4][4][4];
#pragma unroll
    for (int mt = 0; mt < 4; mt++)
#pragma unroll
        for (int nt = 0; nt < 4; nt++)
#pragma unroll
            for (int r = 0; r < 4; r++) acc[mt][nt][r] = 0.0f;

    const int nch = K / 32;
    LOAD_STAGE(0, 0);
    cp_commit();
    if (nch > 1) LOAD_STAGE(1, 32);
    cp_commit();

    int st = 0, ls = 2;
    for (int ch = 0; ch < nch; ch++) {
        cp_wait<1>();
        __syncthreads();
        if (ch + 2 < nch) LOAD_STAGE(ls, (long long)(ch + 2) * 32);
        cp_commit();

        const uint32_t base = sb + (uint32_t)st * STAGE_B;
#pragma unroll
        for (int kk = 0; kk < 2; kk++) {
            uint32_t af[2][4][4];
            uint32_t bfr[2][2][4];
            const uint32_t a_chk = (uint32_t)(kk * 2) + a_chk_l;
            const uint32_t b_chk = (uint32_t)(kk * 2) + b_chk_l;
#pragma unroll
            for (int mt = 0; mt < 4; mt++) {
                const uint32_t ro = swz((uint32_t)(wm * 64 + mt * 16) + a_row_l, a_chk);
                ldsm_x4(af[0][mt], base + 0 * TILE_B + ro);
                ldsm_x4(af[1][mt], base + 1 * TILE_B + ro);
            }
#pragma unroll
            for (int p = 0; p < 2; p++) {
                const uint32_t ro = swz((uint32_t)(wn * 32 + p * 16) + b_row_l, b_chk);
                ldsm_x4(bfr[0][p], base + 2 * TILE_B + ro);
                ldsm_x4(bfr[1][p], base + 3 * TILE_B + ro);
            }
#pragma unroll
            for (int ps = 0; ps < 3; ps++) {
                const int ah = (ps == 2), bh = (ps == 1);
#pragma unroll
                for (int mt = 0; mt < 4; mt++)
#pragma unroll
                    for (int nt = 0; nt < 4; nt++)
                        mma16816(acc[mt][nt], af[ah][mt],
                                 &bfr[bh][nt >> 1][(nt & 1) * 2]);
            }
        }
        st = (st == 2) ? 0 : st + 1;
        ls = (ls == 2) ? 0 : ls + 1;
    }

    // ---- epilogue ----
    const int tq = lane >> 2, tr = lane & 3;
#pragma unroll
    for (int nt = 0; nt < 4; nt++) {
        const int n = n0 + wn * 32 + nt * 8 + tr * 2;
        float b0 = 0.f, b1 = 0.f;
        if (HAS_BIAS) { b0 = bias[n]; b1 = bias[n + 1]; }
#pragma unroll
        for (int mt = 0; mt < 4; mt++) {
            const int m = m0 + wm * 64 + mt * 16 + tq;
            float2 o0, o1;
            o0.x = fmaf(alpha, acc[mt][nt][0], b0);
            o0.y = fmaf(alpha, acc[mt][nt][1], b1);
            o1.x = fmaf(alpha, acc[mt][nt][2], b0);
            o1.y = fmaf(alpha, acc[mt][nt][3], b1);
            const long long r0 = cz + (long long)m * ldc + n;
            const long long r1 = cz + (long long)(m + 8) * ldc + n;
            if (WRITE_F32) {
                *(float2*)(C + r0) = o0;
                *(float2*)(C + r1) = o1;
            }
            if (WRITE_SPLIT) {
                bf16 h0, l0, h1, l1;
                split1(o0.x, h0, l0); split1(o0.y, h1, l1);
                *(uint32_t*)(Oh + r0) = pack2(h0, h1);
                *(uint32_t*)(Ol + r0) = pack2(l0, l1);
                split1(o1.x, h0, l0); split1(o1.y, h1, l1);
                *(uint32_t*)(Oh + r1) = pack2(h0, h1);
                *(uint32_t*)(Ol + r1) = pack2(l0, l1);
            }
        }
    }
#undef LOAD_STAGE
}

// ---------------------------------------------------------------------------
__global__ __launch_bounds__(256)
void split_kernel(const float* __restrict__ in, bf16* __restrict__ oh,
                  bf16* __restrict__ ol)
{
    const size_t i = ((size_t)blockIdx.x * 256 + threadIdx.x) * 4;
    const float4 v = *(const float4*)(in + i);
    bf16 h0, h1, h2, h3, l0, l1, l2, l3;
    split1(v.x, h0, l0); split1(v.y, h1, l1);
    split1(v.z, h2, l2); split1(v.w, h3, l3);
    *(uint2*)(oh + i) = make_uint2(pack2(h0, h1), pack2(h2, h3));
    *(uint2*)(ol + i) = make_uint2(pack2(l0, l1), pack2(l2, l3));
}

// ---------------------------------------------------------------------------
__global__ __launch_bounds__(256)
void transpose_split(const float* __restrict__ in, int ldin, long long sIn,
                     bf16* __restrict__ oh, bf16* __restrict__ ol,
                     int R, long long sOut)
{
    __shared__ float t[32][33];
    in += blockIdx.z * sIn;
    oh += blockIdx.z * sOut;
    ol += blockIdx.z * sOut;
    const int c0 = blockIdx.x * 32, r0 = blockIdx.y * 32;
    const int x = threadIdx.x, y = threadIdx.y;
#pragma unroll
    for (int j = 0; j < 32; j += 8)
        t[y + j][x] = in[(long long)(r0 + y + j) * ldin + c0 + x];
    __syncthreads();
#pragma unroll
    for (int j = 0; j < 32; j += 8) {
        const float v = t[x][y + j];
        bf16 h, l;
        split1(v, h, l);
        oh[(long long)(c0 + y + j) * R + r0 + x] = h;
        ol[(long long)(c0 + y + j) * R + r0 + x] = l;
    }
}

// ---------------------------------------------------------------------------
__global__ __launch_bounds__(256)
void transpose_bf16_2(const bf16* __restrict__ inh, const bf16* __restrict__ inl,
                      int ldin, long long sIn,
                      bf16* __restrict__ oh, bf16* __restrict__ ol,
                      int R, long long sOut)
{
    __shared__ bf16 th[32][33];
    __shared__ bf16 tl[32][33];
    inh += blockIdx.z * sIn;
    inl += blockIdx.z * sIn;
    oh  += blockIdx.z * sOut;
    ol  += blockIdx.z * sOut;
    const int c0 = blockIdx.x * 32, r0 = blockIdx.y * 32;
    const int x = threadIdx.x, y = threadIdx.y;
#pragma unroll
    for (int j = 0; j < 32; j += 8) {
        th[y + j][x] = inh[(long long)(r0 + y + j) * ldin + c0 + x];
        tl[y + j][x] = inl[(long long)(r0 + y + j) * ldin + c0 + x];
    }
    __syncthreads();
#pragma unroll
    for (int j = 0; j < 32; j += 8) {
        oh[(long long)(c0 + y + j) * R + r0 + x] = th[x][y + j];
        ol[(long long)(c0 + y + j) * R + r0 + x] = tl[x][y + j];
    }
}

// ---------------------------------------------------------------------------
__global__ __launch_bounds__(256)
void wvec_kernel(const float* __restrict__ w_qkv, const float* __restrict__ bq,
                 float* __restrict__ wv)
{
    __shared__ float red[8];
    const int d = blockIdx.x;
    const float* rowp = w_qkv + (size_t)d * QKVC + D_;
    float s = 0.0f;
    for (int a = threadIdx.x; a < D_; a += 256) s += rowp[a] * bq[a];
#pragma unroll
    for (int o = 16; o > 0; o >>= 1) s += __shfl_xor_sync(0xffffffffu, s, o);
    if (!(threadIdx.x & 31)) red[threadIdx.x >> 5] = s;
    __syncthreads();
    if (threadIdx.x == 0) {
        float t = 0.0f;
#pragma unroll
        for (int i = 0; i < 8; i++) t += red[i];
        wv[d] = t;
    }
}

// ---------------------------------------------------------------------------
__global__ __launch_bounds__(256)
void cvec_kernel(const float* __restrict__ x, const float* __restrict__ wv,
                 float* __restrict__ c)
{
    const int row = blockIdx.x * 8 + (threadIdx.x >> 5);
    const int lane = threadIdx.x & 31;
    const float* xr = x + (size_t)row * D_;
    float s = 0.0f;
    for (int d = lane; d < D_; d += 32) s += xr[d] * wv[d];
#pragma unroll
    for (int o = 16; o > 0; o >>= 1) s += __shfl_xor_sync(0xffffffffu, s, o);
    if (lane == 0) c[row] = s * SCALE_F;
}

// ---------------------------------------------------------------------------
__global__ __launch_bounds__(256)
void softmax_split_kernel(const float* __restrict__ S, bf16* __restrict__ Sh,
                          bf16* __restrict__ Sl)
{
    const size_t ro = (size_t)blockIdx.x * N_;
    const float* p = S + ro;
    const int tid = threadIdx.x;
    const int w = tid >> 5, l = tid & 31;

    float4 v[4];
#pragma unroll
    for (int i = 0; i < 4; i++)
        v[i] = *(const float4*)(p + (size_t)(tid + i * 256) * 4);

    float m = v[0].x;
#pragma unroll
    for (int i = 0; i < 4; i++) {
        m = fmaxf(m, v[i].x); m = fmaxf(m, v[i].y);
        m = fmaxf(m, v[i].z); m = fmaxf(m, v[i].w);
    }
#pragma unroll
    for (int o = 16; o > 0; o >>= 1)
        m = fmaxf(m, __shfl_xor_sync(0xffffffffu, m, o));

    __shared__ float red[8];
    if (l == 0) red[w] = m;
    __syncthreads();
    float bm = red[0];
#pragma unroll
    for (int i = 1; i < 8; i++) bm = fmaxf(bm, red[i]);
    __syncthreads();

    float s = 0.0f;
#pragma unroll
    for (int i = 0; i < 4; i++) {
        v[i].x = expf(v[i].x - bm); s += v[i].x;
        v[i].y = expf(v[i].y - bm); s += v[i].y;
        v[i].z = expf(v[i].z - bm); s += v[i].z;
        v[i].w = expf(v[i].w - bm); s += v[i].w;
    }
#pragma unroll
    for (int o = 16; o > 0; o >>= 1)
        s += __shfl_xor_sync(0xffffffffu, s, o);
    if (l == 0) red[w] = s;
    __syncthreads();
    float tot = red[0];
#pragma unroll
    for (int i = 1; i < 8; i++) tot += red[i];
    const float inv = 1.0f / tot;

#pragma unroll
    for (int i = 0; i < 4; i++) {
        const size_t o = ro + (size_t)(tid + i * 256) * 4;
        bf16 h0, h1, h2, h3, l0, l1, l2, l3;
        split1(v[i].x * inv, h0, l0);
        split1(v[i].y * inv, h1, l1);
        split1(v[i].z * inv, h2, l2);
        split1(v[i].w * inv, h3, l3);
        *(uint2*)(Sh + o) = make_uint2(pack2(h0, h1), pack2(h2, h3));
        *(uint2*)(Sl + o) = make_uint2(pack2(l0, l1), pack2(l2, l3));
    }
}

// ---------------------------------------------------------------------------
extern "C" void kernel_launch(void* const* d_in, const int* in_sizes, int n_in,
                              void* d_out, int out_size)
{
    const float* x     = (const float*)d_in[0];
    const float* w_qkv = (const float*)d_in[1];
    const float* b_qkv = (const float*)d_in[2];
    const float* w_out = (const float*)d_in[3];
    const float* b_out = (const float*)d_in[4];
    float* out = (float*)d_out;

    float *S, *wv, *cvec;
    bf16 *xh, *xl, *wrh, *wrl, *mth, *mtl, *wvh, *wvl, *vh, *vl, *yh, *yl;
    bf16 *sh, *sl, *vth, *vtl, *ch, *cl, *woh, *wol;
    cudaGetSymbolAddress((void**)&S,    g_s);
    cudaGetSymbolAddress((void**)&wv,   g_wv);
    cudaGetSymbolAddress((void**)&cvec, g_cvec);
    cudaGetSymbolAddress((void**)&xh,   g_xh);  cudaGetSymbolAddress((void**)&xl,  g_xl);
    cudaGetSymbolAddress((void**)&wrh,  g_wrh); cudaGetSymbolAddress((void**)&wrl, g_wrl);
    cudaGetSymbolAddress((void**)&mth,  g_mth); cudaGetSymbolAddress((void**)&mtl, g_mtl);
    cudaGetSymbolAddress((void**)&wvh,  g_wvh); cudaGetSymbolAddress((void**)&wvl, g_wvl);
    cudaGetSymbolAddress((void**)&vh,   g_vh);  cudaGetSymbolAddress((void**)&vl,  g_vl);
    cudaGetSymbolAddress((void**)&yh,   g_yh);  cudaGetSymbolAddress((void**)&yl,  g_yl);
    cudaGetSymbolAddress((void**)&sh,   g_sh);  cudaGetSymbolAddress((void**)&sl,  g_sl);
    cudaGetSymbolAddress((void**)&vth,  g_vth); cudaGetSymbolAddress((void**)&vtl, g_vtl);
    cudaGetSymbolAddress((void**)&ch,   g_ch);  cudaGetSymbolAddress((void**)&cl,  g_cl);
    cudaGetSymbolAddress((void**)&woh,  g_woh); cudaGetSymbolAddress((void**)&wol, g_wol);

    cudaFuncSetAttribute(mma_gemm<true, false, true>,
        cudaFuncAttributeMaxDynamicSharedMemorySize, SMEM_DYN);
    cudaFuncSetAttribute(mma_gemm<false, false, true>,
        cudaFuncAttributeMaxDynamicSharedMemorySize, SMEM_DYN);
    cudaFuncSetAttribute(mma_gemm<true, true, false>,
        cudaFuncAttributeMaxDynamicSharedMemorySize, SMEM_DYN);

    // ONE side stream (R10's known-guard-legal footprint) + events
    static cudaStream_t sv = nullptr;
    static cudaEvent_t eRoot = nullptr, eX = nullptr, eMain = nullptr,
                       eV = nullptr, eSv = nullptr;
    if (!sv) {
        cudaStreamCreateWithFlags(&sv, cudaStreamNonBlocking);
        cudaEventCreateWithFlags(&eRoot, cudaEventDisableTiming);
        cudaEventCreateWithFlags(&eX,    cudaEventDisableTiming);
        cudaEventCreateWithFlags(&eMain, cudaEventDisableTiming);
        cudaEventCreateWithFlags(&eV,    cudaEventDisableTiming);
        cudaEventCreateWithFlags(&eSv,   cudaEventDisableTiming);
    }

    const dim3 blk(256);
    const dim3 tblk(32, 8);
    const long long ND = (long long)N_ * D_;
    const long long NN = (long long)N_ * N_;
    const long long DN = (long long)D_ * N_;

    // ---- fork sv ----
    cudaEventRecord(eRoot, 0);
    cudaStreamWaitEvent(sv, eRoot, 0);

    // sv: weight transposes (inputs only)
    transpose_split<<<dim3(D_ / 32, D_ / 32, 1), tblk, 0, sv>>>(
        w_qkv + 2 * D_, QKVC, 0, wvh, wvl, D_, 0);                // Wv^T
    transpose_split<<<dim3(D_ / 32, D_ / 32, 1), tblk, 0, sv>>>(
        w_out, D_, 0, woh, wol, D_, 0);                           // Wo^T

    // main: x split, weight row split, bias vectors, Mt
    split_kernel<<<(B_ * N_ * D_) / 1024, blk>>>(x, xh, xl);
    cudaEventRecord(eX, 0);
    split_kernel<<<(D_ * QKVC) / 1024, blk>>>(w_qkv, wrh, wrl);
    wvec_kernel<<<D_, blk>>>(w_qkv, b_qkv, wv);
    cvec_kernel<<<(B_ * N_) / 8, blk>>>(x, wv, cvec);
    mma_gemm<false, false, true><<<dim3(D_ / 128, D_ / 128, 1), blk, SMEM_DYN>>>(
        wrh + D_, wrl + D_, wrh, wrl, nullptr, nullptr, mth, mtl,
        D_, QKVC, QKVC, D_, 0, 0, 0, 0, 1.0f);
    cudaEventRecord(eMain, 0);   // covers xh/xl, cvec, Mt

    // sv: V GEMM + V^T (needs xh/xl)
    cudaStreamWaitEvent(sv, eX, 0);
    mma_gemm<true, false, true><<<dim3(D_ / 128, (B_ * N_) / 128, 1), blk, SMEM_DYN, sv>>>(
        xh, xl, wvh, wvl, b_qkv + 2 * D_, nullptr, vh, vl,
        D_, D_, D_, D_, 0, 0, 0, 0, 1.0f);
    transpose_bf16_2<<<dim3(D_ / 32, N_ / 32, B_), tblk, 0, sv>>>(
        vh, vl, D_, ND, vth, vtl, N_, DN);
    cudaEventRecord(eV, sv);

    // ---- per-batch chains: batches 0,2 on stream 0; batches 1,3 on sv ----
    cudaStreamWaitEvent(0,  eV,    0);   // stream-0 chains need V^T for PV
    cudaStreamWaitEvent(sv, eMain, 0);   // sv chains need Mt/cvec

    for (int b = 0; b < B_; b++) {
        cudaStream_t cs = (b & 1) ? sv : (cudaStream_t)0;
        const long long oND = (long long)b * ND;
        const long long oNN = (long long)b * NN;
        const long long oDN = (long long)b * DN;

        // y_b = x_b @ Mt^T
        mma_gemm<false, false, true><<<dim3(D_ / 128, N_ / 128, 1), blk, SMEM_DYN, cs>>>(
            xh + oND, xl + oND, mth, mtl, nullptr, nullptr, yh + oND, yl + oND,
            D_, D_, D_, D_, 0, 0, 0, 0, 1.0f);

        // S_b = scale*(y_b x_b^T) + cvec_b
        mma_gemm<true, true, false><<<dim3(N_ / 128, N_ / 128, 1), blk, SMEM_DYN, cs>>>(
            yh + oND, yl + oND, xh + oND, xl + oND, cvec + (long long)b * N_,
            S + oNN, nullptr, nullptr,
            D_, D_, D_, N_, 0, 0, 0, 0, SCALE_F);

        // softmax_b + split
        softmax_split_kernel<<<N_, blk, 0, cs>>>(S + oNN, sh + oNN, sl + oNN);

        // PV_b
        mma_gemm<false, false, true><<<dim3(D_ / 128, N_ / 128, 1), blk, SMEM_DYN, cs>>>(
            sh + oNN, sl + oNN, vth + oDN, vtl + oDN, nullptr, nullptr,
            ch + oND, cl + oND, N_, N_, N_, D_, 0, 0, 0, 0, 1.0f);

        // out_b = ctx_b @ Wo + bo
        mma_gemm<true, true, false><<<dim3(D_ / 128, N_ / 128, 1), blk, SMEM_DYN, cs>>>(
            ch + oND, cl + oND, woh, wol, b_out, out + oND, nullptr, nullptr,
            D_, D_, D_, D_, 0, 0, 0, 0, 1.0f);
    }

    // ---- join sv back to the capture stream ----
    cudaEventRecord(eSv, sv);
    cudaStreamWaitEvent(0, eSv, 0);
}